// round 15
// baseline (speedup 1.0000x reference)
#include <cuda_runtime.h>
#include <cuda_bf16.h>
#include <math.h>
#include <stdint.h>

#define NNODES 50000
#define NEDGES 800000
#define HID 128
#define EDIM 16
#define NL 3
#define NG 256
#define BN_EPS 1e-5f
#define MTILES 391            // ceil(50000/128)
#define TILE_ELEMS 16384      // 128x128
#define NBTILES 22            // 1 lin + 12 pack + 9 w2i
#define NPAD (MTILES * 128 - NNODES)   // 48 padding rows

// ------------------------- scratch (static device globals) -------------------
__device__ float g_h[NNODES * HID];
__device__ float g_p[NNODES * HID];
__device__ float g_gh[NNODES * 3 * HID];
__device__ float g_deg[NNODES];
__device__ float g_w2i[NL * HID * 3 * HID];
__device__ float g_c2i[NL * 3 * HID];
__device__ float g_packb[NL * HID * 512];
__device__ float g_wihT[NL * HID * 384];
__device__ float g_packbias[NL * 512];
__device__ float g_zsum[NG * HID];
__device__ unsigned g_zmaxk[NG * HID];
__device__ float g_cnt[NG];
// CSR (dst-sorted edge list)
__device__ int g_cnt_i[NNODES];
__device__ int g_off[NNODES];
__device__ int g_cur[NNODES];
__device__ int g_blk[64];
__device__ int g_eid[NEDGES];
__device__ int g_esrc[NEDGES];
// bf16 split operand buffers (pre-swizzled tile layout)
__device__ __nv_bfloat16 g_ah[MTILES * TILE_ELEMS];
__device__ __nv_bfloat16 g_al[MTILES * TILE_ELEMS];
__device__ __nv_bfloat16 g_sh[MTILES * TILE_ELEMS];
__device__ __nv_bfloat16 g_sl[MTILES * TILE_ELEMS];
__device__ __nv_bfloat16 g_bh[NBTILES * TILE_ELEMS];
__device__ __nv_bfloat16 g_bl[NBTILES * TILE_ELEMS];

// ------------------------- helpers ------------------------------------------
__device__ __forceinline__ unsigned long long pk2(float lo, float hi) {
    unsigned long long r;
    asm("mov.b64 %0, {%1, %2};" : "=l"(r) : "f"(lo), "f"(hi));
    return r;
}
__device__ __forceinline__ void unpk2(unsigned long long v, float& lo, float& hi) {
    asm("mov.b64 {%0, %1}, %2;" : "=f"(lo), "=f"(hi) : "l"(v));
}
#define FMA2(acc, a, b) asm("fma.rn.f32x2 %0, %1, %2, %0;" : "+l"(acc) : "l"(a), "l"(b))
__device__ __forceinline__ float sigm(float x) { return 1.f / (1.f + __expf(-x)); }

__device__ __forceinline__ unsigned smem_u32(const void* p) {
    unsigned a;
    asm("{ .reg .u64 t; cvta.to.shared.u64 t, %1; cvt.u32.u64 %0, t; }" : "=r"(a) : "l"(p));
    return a;
}
__device__ __forceinline__ unsigned pb2(float a, float b) {
    __nv_bfloat162 t = __floats2bfloat162_rn(a, b);
    return *reinterpret_cast<unsigned*>(&t);
}
// swizzled 16B-granule index within a 128x128 bf16 tile
__device__ __forceinline__ int swz_g(int r, int c8) { return r * 16 + (c8 ^ (r & 7)); }
__device__ __forceinline__ int swz_idx(int r, int c8) { return swz_g(r, c8) * 8; }

__device__ __forceinline__ void split8(const float* o, uint4& uh, uint4& ul) {
    float lf[8];
#pragma unroll
    for (int i = 0; i < 8; i++)
        lf[i] = o[i] - __bfloat162float(__float2bfloat16_rn(o[i]));
    uh.x = pb2(o[0], o[1]); uh.y = pb2(o[2], o[3]);
    uh.z = pb2(o[4], o[5]); uh.w = pb2(o[6], o[7]);
    ul.x = pb2(lf[0], lf[1]); ul.y = pb2(lf[2], lf[3]);
    ul.z = pb2(lf[4], lf[5]); ul.w = pb2(lf[6], lf[7]);
}

#define LDSM4(r0, r1, r2, r3, addr) \
    asm volatile("ldmatrix.sync.aligned.m8n8.x4.shared.b16 {%0,%1,%2,%3}, [%4];" \
                 : "=r"(r0), "=r"(r1), "=r"(r2), "=r"(r3) : "r"(addr))

#define MMA16816(c, a0, a1, a2, a3, b0, b1) \
    asm volatile("mma.sync.aligned.m16n8k16.row.col.f32.bf16.bf16.f32 " \
                 "{%0,%1,%2,%3}, {%4,%5,%6,%7}, {%8,%9}, {%0,%1,%2,%3};" \
                 : "+f"((c)[0]), "+f"((c)[1]), "+f"((c)[2]), "+f"((c)[3]) \
                 : "r"(a0), "r"(a1), "r"(a2), "r"(a3), "r"(b0), "r"(b1))

#define CPA16(dst, src) \
    asm volatile("cp.async.cg.shared.global [%0], [%1], 16;" :: "r"(dst), "l"(src))
#define CPA_COMMIT() asm volatile("cp.async.commit_group;" ::: "memory")
#define CPA_WAIT0() asm volatile("cp.async.wait_group 0;" ::: "memory")
#define CPA_WAIT1() asm volatile("cp.async.wait_group 1;" ::: "memory")

// shared 3-term MMA pass over one 128x128 A/B tile pair (bf16 split)
__device__ __forceinline__ void mm_pass(
    float (&acc)[2][4][4],
    unsigned uAhi, unsigned uAlo, unsigned uBhi, unsigned uBlo,
    int a_r, int a_cg, int b_r, int b_cg)
{
#pragma unroll
    for (int mi = 0; mi < 2; mi++)
#pragma unroll
        for (int ni = 0; ni < 4; ni++)
#pragma unroll
            for (int j = 0; j < 4; j++) acc[mi][ni][j] = 0.f;
#pragma unroll
    for (int kc = 0; kc < 8; kc++) {
        unsigned ah[2][4], al[2][4], bh[2][4], bl[2][4];
#pragma unroll
        for (int mi = 0; mi < 2; mi++) {
            int soff = swz_g(a_r + mi * 16, kc * 2 + a_cg) * 16;
            LDSM4(ah[mi][0], ah[mi][1], ah[mi][2], ah[mi][3], uAhi + soff);
            LDSM4(al[mi][0], al[mi][1], al[mi][2], al[mi][3], uAlo + soff);
        }
#pragma unroll
        for (int nb = 0; nb < 2; nb++) {
            int soff = swz_g(b_r + nb * 16, kc * 2 + b_cg) * 16;
            LDSM4(bh[nb][0], bh[nb][1], bh[nb][2], bh[nb][3], uBhi + soff);
            LDSM4(bl[nb][0], bl[nb][1], bl[nb][2], bl[nb][3], uBlo + soff);
        }
#pragma unroll
        for (int mi = 0; mi < 2; mi++) {
#pragma unroll
            for (int ni = 0; ni < 4; ni++) {
                int nb = ni >> 1;
                int of = (ni & 1) * 2;
                MMA16816(acc[mi][ni], ah[mi][0], ah[mi][1], ah[mi][2], ah[mi][3],
                         bh[nb][of], bh[nb][of + 1]);
                MMA16816(acc[mi][ni], ah[mi][0], ah[mi][1], ah[mi][2], ah[mi][3],
                         bl[nb][of], bl[nb][of + 1]);
                MMA16816(acc[mi][ni], al[mi][0], al[mi][1], al[mi][2], al[mi][3],
                         bh[nb][of], bh[nb][of + 1]);
            }
        }
    }
}

// ------------------------- tensor-core GEMM (mma.sync bf16) ------------------
// R8 shape: 512 threads = 16 warps (4x4); warp tile 32x32. Fused 3-term k-loop.
__global__ __launch_bounds__(512, 1) void tgemm(
    const __nv_bfloat16* __restrict__ Ahi, const __nv_bfloat16* __restrict__ Alo,
    int btile0,
    float* __restrict__ C0, int ld0, int ny0, float* __restrict__ C1, int ld1,
    const float* __restrict__ bias, int do_relu)
{
    extern __shared__ __align__(16) char rawsm[];
    unsigned ubase = smem_u32(rawsm);
    unsigned uAst[2] = {ubase, ubase + 65536};
    unsigned uBhi = ubase + 131072, uBlo = ubase + 163840;

    int tid = threadIdx.x;
    int warp = tid >> 5;
    int lane = tid & 31;
    int wm = warp & 3;
    int wn = warp >> 2;

    {
        int bt = btile0 + blockIdx.y;
        const uint4* gh4 = (const uint4*)(g_bh + (size_t)bt * TILE_ELEMS);
        const uint4* gl4 = (const uint4*)(g_bl + (size_t)bt * TILE_ELEMS);
#pragma unroll
        for (int i = tid; i < 2048; i += 512) {
            CPA16(uBhi + i * 16, gh4 + i);
            CPA16(uBlo + i * 16, gl4 + i);
        }
    }
    if ((int)blockIdx.x < MTILES) {
        const uint4* gh4 = (const uint4*)(Ahi + (size_t)blockIdx.x * TILE_ELEMS);
        const uint4* gl4 = (const uint4*)(Alo + (size_t)blockIdx.x * TILE_ELEMS);
#pragma unroll
        for (int i = tid; i < 2048; i += 512) {
            CPA16(uAst[0] + i * 16, gh4 + i);
            CPA16(uAst[0] + 32768 + i * 16, gl4 + i);
        }
    }
    CPA_COMMIT();

    float* Cp;
    int tcol, ldc;
    if ((int)blockIdx.y < ny0) { Cp = C0; tcol = blockIdx.y * 128; ldc = ld0; }
    else { Cp = C1; tcol = (blockIdx.y - ny0) * 128; ldc = ld1; }
    int gcb = blockIdx.y * 128;

    int a_r = wm * 32 + (lane & 7) + 8 * ((lane >> 3) & 1);
    int a_cg = lane >> 4;
    int b_r = wn * 32 + (lane & 7) + 8 * (lane >> 4);
    int b_cg = (lane >> 3) & 1;
    int t4 = lane >> 2;
    int t2 = (lane & 3) * 2;

    int stage = 0;
    for (int mt = blockIdx.x; mt < MTILES; mt += gridDim.x) {
        CPA_WAIT0();
        __syncthreads();

        int nxt = mt + gridDim.x;
        if (nxt < MTILES) {
            const uint4* gh4 = (const uint4*)(Ahi + (size_t)nxt * TILE_ELEMS);
            const uint4* gl4 = (const uint4*)(Alo + (size_t)nxt * TILE_ELEMS);
            unsigned ud = uAst[stage ^ 1];
#pragma unroll
            for (int i = tid; i < 2048; i += 512) {
                CPA16(ud + i * 16, gh4 + i);
                CPA16(ud + 32768 + i * 16, gl4 + i);
            }
        }
        CPA_COMMIT();

        float acc[2][4][4];
        mm_pass(acc, uAst[stage], uAst[stage] + 32768, uBhi, uBlo,
                a_r, a_cg, b_r, b_cg);

#pragma unroll
        for (int mi = 0; mi < 2; mi++) {
#pragma unroll
            for (int half = 0; half < 2; half++) {
                int r_in = wm * 32 + mi * 16 + t4 + half * 8;
                int grow = mt * 128 + r_in;
                if (grow >= NNODES) continue;
                float* cp = Cp + (size_t)grow * ldc + tcol;
#pragma unroll
                for (int ni = 0; ni < 4; ni++) {
                    int lc = wn * 32 + ni * 8 + t2;
                    float v0 = acc[mi][ni][half * 2 + 0] + bias[gcb + lc];
                    float v1 = acc[mi][ni][half * 2 + 1] + bias[gcb + lc + 1];
                    if (do_relu) { v0 = fmaxf(v0, 0.f); v1 = fmaxf(v1, 0.f); }
                    *(float2*)(cp + lc) = make_float2(v0, v1);
                }
            }
        }
        stage ^= 1;
    }
}

// ------------------------- fused GI GEMM + GRU gate + BN + residual ----------
// grid (148,1); per m-tile: A (S tiles) single-buffered, B (w2i tiles y=0..2)
// double-buffered; ir/iz/in frags stay in this thread's registers across y.
__global__ __launch_bounds__(512, 1) void gigate(
    const __nv_bfloat16* __restrict__ Shi, const __nv_bfloat16* __restrict__ Slo,
    int btile0,
    const float* __restrict__ bih, const float* __restrict__ c2i,
    const float* __restrict__ gamma, const float* __restrict__ beta,
    const float* __restrict__ mean, const float* __restrict__ var,
    int write_tiles)
{
    extern __shared__ __align__(16) char rawsm[];
    unsigned ubase = smem_u32(rawsm);
    unsigned uAhi = ubase, uAlo = ubase + 32768;
    unsigned uB0hi = ubase + 65536,  uB0lo = ubase + 98304;
    unsigned uB1hi = ubase + 131072, uB1lo = ubase + 163840;

    int tid = threadIdx.x;
    int warp = tid >> 5;
    int lane = tid & 31;
    int wm = warp & 3;
    int wn = warp >> 2;

    int a_r = wm * 32 + (lane & 7) + 8 * ((lane >> 3) & 1);
    int a_cg = lane >> 4;
    int b_r = wn * 32 + (lane & 7) + 8 * (lane >> 4);
    int b_cg = (lane >> 3) & 1;
    int t4 = lane >> 2;
    int t2 = (lane & 3) * 2;

    for (int mt = blockIdx.x; mt < MTILES; mt += gridDim.x) {
        __syncthreads();   // previous tile fully done before overwriting A
        // issue A + B(y0) -> group1 ; B(y1) -> group2
        {
            const uint4* ah4 = (const uint4*)(Shi + (size_t)mt * TILE_ELEMS);
            const uint4* al4 = (const uint4*)(Slo + (size_t)mt * TILE_ELEMS);
            const uint4* b0h = (const uint4*)(g_bh + (size_t)(btile0 + 0) * TILE_ELEMS);
            const uint4* b0l = (const uint4*)(g_bl + (size_t)(btile0 + 0) * TILE_ELEMS);
#pragma unroll
            for (int i = tid; i < 2048; i += 512) {
                CPA16(uAhi + i * 16, ah4 + i);
                CPA16(uAlo + i * 16, al4 + i);
                CPA16(uB0hi + i * 16, b0h + i);
                CPA16(uB0lo + i * 16, b0l + i);
            }
            CPA_COMMIT();
            const uint4* b1h = (const uint4*)(g_bh + (size_t)(btile0 + 1) * TILE_ELEMS);
            const uint4* b1l = (const uint4*)(g_bl + (size_t)(btile0 + 1) * TILE_ELEMS);
#pragma unroll
            for (int i = tid; i < 2048; i += 512) {
                CPA16(uB1hi + i * 16, b1h + i);
                CPA16(uB1lo + i * 16, b1l + i);
            }
            CPA_COMMIT();
        }
        CPA_WAIT1();       // A + B0 ready
        __syncthreads();

        float accR[2][4][4];
        mm_pass(accR, uAhi, uAlo, uB0hi, uB0lo, a_r, a_cg, b_r, b_cg);
        __syncthreads();   // done reading B0 buffer

        {
            const uint4* b2h = (const uint4*)(g_bh + (size_t)(btile0 + 2) * TILE_ELEMS);
            const uint4* b2l = (const uint4*)(g_bl + (size_t)(btile0 + 2) * TILE_ELEMS);
#pragma unroll
            for (int i = tid; i < 2048; i += 512) {
                CPA16(uB0hi + i * 16, b2h + i);
                CPA16(uB0lo + i * 16, b2l + i);
            }
            CPA_COMMIT();
        }
        CPA_WAIT1();       // B1 ready (B2 may be in flight)
        __syncthreads();

        float accZ[2][4][4];
        mm_pass(accZ, uAhi, uAlo, uB1hi, uB1lo, a_r, a_cg, b_r, b_cg);

        CPA_WAIT0();       // B2 ready
        __syncthreads();

        float accN[2][4][4];
        mm_pass(accN, uAhi, uAlo, uB0hi, uB0lo, a_r, a_cg, b_r, b_cg);

        // fused epilogue: GRU gates + BN + residual
#pragma unroll
        for (int mi = 0; mi < 2; mi++) {
#pragma unroll
            for (int half = 0; half < 2; half++) {
                int r_in = wm * 32 + mi * 16 + t4 + half * 8;
                int grow = mt * 128 + r_in;
                if (grow >= NNODES) continue;
                float dg = __ldg(g_deg + grow);
                const float* ghp = g_gh + (size_t)grow * 384;
                float* hp = g_h + (size_t)grow * HID;
#pragma unroll
                for (int ni = 0; ni < 4; ni++) {
                    int lc = wn * 32 + ni * 8 + t2;
                    float ov[2];
#pragma unroll
                    for (int c = 0; c < 2; c++) {
                        int j = lc + c;
                        float ir = accR[mi][ni][half * 2 + c] + __ldg(bih + j)
                                   + dg * __ldg(c2i + j);
                        float iz = accZ[mi][ni][half * 2 + c] + __ldg(bih + 128 + j)
                                   + dg * __ldg(c2i + 128 + j);
                        float inn = accN[mi][ni][half * 2 + c] + __ldg(bih + 256 + j)
                                    + dg * __ldg(c2i + 256 + j);
                        float hr = __ldg(ghp + j);
                        float hz = __ldg(ghp + 128 + j);
                        float hn = __ldg(ghp + 256 + j);
                        float hv = __ldg(hp + j);
                        float r = sigm(ir + hr);
                        float z = sigm(iz + hz);
                        float nn = tanhf(inn + r * hn);
                        float hnew = (1.f - z) * nn + z * hv;
                        float bn = (hnew - __ldg(mean + j)) * rsqrtf(__ldg(var + j) + BN_EPS)
                                   * __ldg(gamma + j) + __ldg(beta + j);
                        ov[c] = hv + bn;
                    }
                    *(float2*)(hp + lc) = make_float2(ov[0], ov[1]);
                    if (write_tiles) {
                        float l0 = ov[0] - __bfloat162float(__float2bfloat16_rn(ov[0]));
                        float l1 = ov[1] - __bfloat162float(__float2bfloat16_rn(ov[1]));
                        int didx = mt * TILE_ELEMS + swz_idx(r_in, lc >> 3) + (lc & 7);
                        *(unsigned*)(g_ah + didx) = pb2(ov[0], ov[1]);
                        *(unsigned*)(g_al + didx) = pb2(l0, l1);
                    }
                }
            }
        }
    }
}

// ------------------------- fp32 sgemm (w2i prep only) ------------------------
#define BM 128
#define BN 128
#define BK 16
__device__ __forceinline__ int ASW(int k, int m) { return m ^ ((k * 8) & 127); }

__global__ __launch_bounds__(256, 2) void sgemm128(
    const float* __restrict__ A, const float* __restrict__ B,
    int M, int N, float* __restrict__ C0,
    int batchA, int batchB, int batchC)
{
    __shared__ unsigned long long As2[BK][BM];
    __shared__ float Bs[BK][BN];
    A += (size_t)blockIdx.z * batchA;
    B += (size_t)blockIdx.z * batchB;
    C0 += (size_t)blockIdx.z * batchC;
    int m0 = blockIdx.x * BM, n0 = blockIdx.y * BN;
    int t = threadIdx.x, rg = t >> 4, cg = t & 15;
    unsigned long long acc[8][4];
#pragma unroll
    for (int r = 0; r < 8; r++)
#pragma unroll
        for (int p = 0; p < 4; p++) acc[r][p] = 0ull;
#pragma unroll 1
    for (int k0 = 0; k0 < 128; k0 += BK) {
#pragma unroll
        for (int i = 0; i < 2; i++) {
            int id = t + i * 256, row = id >> 2, kk4 = (id & 3) * 4;
            float4 v = make_float4(0.f, 0.f, 0.f, 0.f);
            int gm = m0 + row;
            if (gm < M) v = *(const float4*)(A + (size_t)gm * 128 + k0 + kk4);
            As2[kk4 + 0][ASW(kk4 + 0, row)] = pk2(v.x, v.x);
            As2[kk4 + 1][ASW(kk4 + 1, row)] = pk2(v.y, v.y);
            As2[kk4 + 2][ASW(kk4 + 2, row)] = pk2(v.z, v.z);
            As2[kk4 + 3][ASW(kk4 + 3, row)] = pk2(v.w, v.w);
        }
#pragma unroll
        for (int i = 0; i < 2; i++) {
            int id = t + i * 256, row = id >> 5, nn = (id & 31) * 4;
            *(float4*)&Bs[row][nn] = *(const float4*)(B + (size_t)(k0 + row) * N + n0 + nn);
        }
        __syncthreads();
#pragma unroll
        for (int k = 0; k < BK; k++) {
            int ms = ASW(k, rg * 8);
            ulonglong2 a01 = *(const ulonglong2*)&As2[k][ms];
            ulonglong2 a23 = *(const ulonglong2*)&As2[k][ms + 2];
            ulonglong2 a45 = *(const ulonglong2*)&As2[k][ms + 4];
            ulonglong2 a67 = *(const ulonglong2*)&As2[k][ms + 6];
            ulonglong2 b01 = *(const ulonglong2*)&Bs[k][cg * 8];
            ulonglong2 b23 = *(const ulonglong2*)&Bs[k][cg * 8 + 4];
            unsigned long long av[8] = {a01.x, a01.y, a23.x, a23.y, a45.x, a45.y, a67.x, a67.y};
            unsigned long long bv[4] = {b01.x, b01.y, b23.x, b23.y};
#pragma unroll
            for (int r = 0; r < 8; r++)
#pragma unroll
                for (int p = 0; p < 4; p++) FMA2(acc[r][p], av[r], bv[p]);
        }
        __syncthreads();
    }
    int nbase = n0 + cg * 8;
#pragma unroll
    for (int r = 0; r < 8; r++) {
        int gm = m0 + rg * 8 + r;
        if (gm >= M) break;
        float c[8];
#pragma unroll
        for (int p = 0; p < 4; p++) unpk2(acc[r][p], c[2 * p], c[2 * p + 1]);
        *(float4*)(C0 + (size_t)gm * N + nbase) = make_float4(c[0], c[1], c[2], c[3]);
        *(float4*)(C0 + (size_t)gm * N + nbase + 4) = make_float4(c[4], c[5], c[6], c[7]);
    }
}

// ------------------------- prep kernel ---------------------------------------
__global__ void prep_kernel(const float* __restrict__ msg_w1, const float* __restrict__ msg_b1,
                            const float* __restrict__ whh, const float* __restrict__ bhh,
                            const float* __restrict__ wih, const float* __restrict__ msg_b2,
                            const float* __restrict__ x)
{
    int idx = blockIdx.x * blockDim.x + threadIdx.x;
    if (idx < NL * HID * 512) {
        int l = idx / (HID * 512);
        int r = idx % (HID * 512);
        int k = r / 512, c = r % 512;
        float v;
        if (c < HID) v = msg_w1[l * 144 * HID + k * HID + c];
        else v = whh[l * 384 * HID + (c - HID) * HID + k];
        g_packb[idx] = v;
    }
    if (idx < NL * HID * 384) {
        int l = idx / (HID * 384);
        int r = idx % (HID * 384);
        int o = r / 384, g = r % 384;
        g_wihT[idx] = wih[l * 384 * HID + g * HID + o];
    }
    if (idx < NL * 512) {
        int l = idx / 512, c = idx % 512;
        g_packbias[idx] = (c < HID) ? msg_b1[l * HID + c] : bhh[l * 384 + (c - HID)];
    }
    if (idx < NL * 384) {
        int l = idx / 384, g = idx % 384;
        const float* wr = wih + l * 384 * HID + g * HID;
        const float* b2 = msg_b2 + l * HID;
        float acc = 0.f;
#pragma unroll 8
        for (int j = 0; j < HID; j++) acc += b2[j] * __ldg(wr + j);
        g_c2i[idx] = acc;
    }
    if (idx < NNODES) g_cnt_i[idx] = 0;
    if (idx < NG * HID) { g_zsum[idx] = 0.f; g_zmaxk[idx] = 0u; }
    if (idx < NG) g_cnt[idx] = 0.f;
    if (idx < NPAD * 16) {
        int row = NNODES + idx / 16;
        int kg = idx % 16;
        int didx = (row >> 7) * TILE_ELEMS + swz_idx(row & 127, kg);
        uint4 z = make_uint4(0u, 0u, 0u, 0u);
        *(uint4*)(g_sh + didx) = z;
        *(uint4*)(g_sl + didx) = z;
    }
    if (idx < MTILES * 128 * 16) {
        int row = idx >> 4;
        int kg = idx & 15;
        float o[8];
        if (row < NNODES) {
            float4 a = *(const float4*)(x + (size_t)row * HID + kg * 8);
            float4 b = *(const float4*)(x + (size_t)row * HID + kg * 8 + 4);
            o[0] = a.x; o[1] = a.y; o[2] = a.z; o[3] = a.w;
            o[4] = b.x; o[5] = b.y; o[6] = b.z; o[7] = b.w;
        } else {
#pragma unroll
            for (int i = 0; i < 8; i++) o[i] = 0.f;
        }
        uint4 uh, ul;
        split8(o, uh, ul);
        int didx = (row >> 7) * TILE_ELEMS + swz_idx(row & 127, kg);
        *(uint4*)(g_ah + didx) = uh;
        *(uint4*)(g_al + didx) = ul;
    }
}

// convert all B weight tiles to swizzled bf16 hi/lo (tile layout [n][k])
__global__ void prep_convB(const float* __restrict__ lin_w) {
    int idx = blockIdx.x * blockDim.x + threadIdx.x;
    if (idx >= NBTILES * 2048) return;
    int tile = idx / 2048;
    int r = idx % 2048;
    int n_in = r >> 4;
    int kg = r & 15;
    float o[8];
#pragma unroll
    for (int i = 0; i < 8; i++) {
        int k = kg * 8 + i;
        float v;
        if (tile == 0) {
            v = lin_w[k * HID + n_in];
        } else if (tile < 13) {
            int l = (tile - 1) >> 2, j = (tile - 1) & 3;
            v = g_packb[l * (HID * 512) + k * 512 + j * 128 + n_in];
        } else {
            int l = (tile - 13) / 3, j = (tile - 13) % 3;
            v = g_w2i[(l * HID + k) * 384 + j * 128 + n_in];
        }
        o[i] = v;
    }
    uint4 uh, ul;
    split8(o, uh, ul);
    int didx = tile * TILE_ELEMS + swz_idx(n_in, kg);
    *(uint4*)(g_bh + didx) = uh;
    *(uint4*)(g_bl + didx) = ul;
}

// convert fp32 row-major [rows,128] -> swizzled bf16 hi/lo tiles (coalesced 16B)
__global__ void conv_rows(const float* __restrict__ src,
                          __nv_bfloat16* __restrict__ dhi, __nv_bfloat16* __restrict__ dlo)
{
    int idx = blockIdx.x * blockDim.x + threadIdx.x;
    if (idx >= MTILES * 128 * 16) return;
    int row = idx >> 4;
    int kg = idx & 15;
    float o[8];
    if (row < NNODES) {
        float4 a = *(const float4*)(src + (size_t)row * HID + kg * 8);
        float4 b = *(const float4*)(src + (size_t)row * HID + kg * 8 + 4);
        o[0] = a.x; o[1] = a.y; o[2] = a.z; o[3] = a.w;
        o[4] = b.x; o[5] = b.y; o[6] = b.z; o[7] = b.w;
    } else {
#pragma unroll
        for (int i = 0; i < 8; i++) o[i] = 0.f;
    }
    uint4 uh, ul;
    split8(o, uh, ul);
    int didx = (row >> 7) * TILE_ELEMS + swz_idx(row & 127, kg);
    *(uint4*)(dhi + didx) = uh;
    *(uint4*)(dlo + didx) = ul;
}

// ------------------------- CSR build -----------------------------------------
__global__ void csr_count(const int* __restrict__ dst) {
    int e = blockIdx.x * blockDim.x + threadIdx.x;
    if (e < NEDGES) atomicAdd(&g_cnt_i[dst[e]], 1);
}

__global__ __launch_bounds__(1024) void csr_scan1() {
    __shared__ int s[1024];
    int tid = threadIdx.x;
    int i = blockIdx.x * 1024 + tid;
    int c = (i < NNODES) ? g_cnt_i[i] : 0;
    s[tid] = c;
    __syncthreads();
#pragma unroll
    for (int off = 1; off < 1024; off <<= 1) {
        int v = (tid >= off) ? s[tid - off] : 0;
        __syncthreads();
        s[tid] += v;
        __syncthreads();
    }
    if (i < NNODES) g_off[i] = s[tid] - c;
    if (tid == 1023) g_blk[blockIdx.x] = s[1023];
}

__global__ void csr_scan2(int nblk) {
    __shared__ int s[64];
    int t = threadIdx.x;
    int v = (t < nblk) ? g_blk[t] : 0;
    s[t] = v;
    __syncthreads();
#pragma unroll
    for (int off = 1; off < 64; off <<= 1) {
        int u = (t >= off) ? s[t - off] : 0;
        __syncthreads();
        s[t] += u;
        __syncthreads();
    }
    if (t < nblk) g_blk[t] = s[t] - v;
}

__global__ void csr_final() {
    int i = blockIdx.x * blockDim.x + threadIdx.x;
    if (i >= NNODES) return;
    int base = g_off[i] + g_blk[i >> 10];
    g_off[i] = base;
    g_cur[i] = base;
    g_deg[i] = (float)g_cnt_i[i];
}

__global__ void csr_fill(const int* __restrict__ src, const int* __restrict__ dst) {
    int e = blockIdx.x * blockDim.x + threadIdx.x;
    if (e >= NEDGES) return;
    int d = dst[e];
    int pos = atomicAdd(&g_cur[d], 1);
    g_eid[pos] = e;
    g_esrc[pos] = src[e];
}

// ------------------------- CSR gather-aggregate (R8 form) --------------------
__global__ __launch_bounds__(256) void agg_kernel(
    const float* __restrict__ ea, const float* __restrict__ w1b)
{
    int lane = threadIdx.x & 31;
    int n = (blockIdx.x * blockDim.x + threadIdx.x) >> 5;
    if (n >= NNODES) return;

    unsigned long long w0[16], w1[16];
#pragma unroll
    for (int t = 0; t < 16; t++) {
        float4 w = *(const float4*)(w1b + t * HID + lane * 4);
        w0[t] = pk2(w.x, w.y);
        w1[t] = pk2(w.z, w.w);
    }

    int base = g_off[n];
    int cnt = g_cnt_i[n];
    float acc0 = 0.f, acc1 = 0.f, acc2 = 0.f, acc3 = 0.f;

    for (int i = 0; i < cnt; i++) {
        int e = __ldg(g_eid + base + i);
        int s = __ldg(g_esrc + base + i);
        const float4* eap = (const float4*)(ea + (size_t)e * EDIM);
        float4 e0 = __ldg(eap + 0), e1 = __ldg(eap + 1);
        float4 e2 = __ldg(eap + 2), e3 = __ldg(eap + 3);
        ulonglong2 p2 = *(const ulonglong2*)(g_p + (size_t)s * HID + lane * 4);
        unsigned long long a0 = p2.x, a1 = p2.y;
        float ec[16] = {e0.x, e0.y, e0.z, e0.w, e1.x, e1.y, e1.z, e1.w,
                        e2.x, e2.y, e2.z, e2.w, e3.x, e3.y, e3.z, e3.w};
#pragma unroll
        for (int t = 0; t < 16; t++) {
            unsigned long long et = pk2(ec[t], ec[t]);
            FMA2(a0, w0[t], et);
            FMA2(a1, w1[t], et);
        }
        float x0, x1, x2, x3;
        unpk2(a0, x0, x1);
        unpk2(a1, x2, x3);
        acc0 += fmaxf(x0, 0.f);
        acc1 += fmaxf(x1, 0.f);
        acc2 += fmaxf(x2, 0.f);
        acc3 += fmaxf(x3, 0.f);
    }

    float l0 = acc0 - __bfloat162float(__float2bfloat16_rn(acc0));
    float l1 = acc1 - __bfloat162float(__float2bfloat16_rn(acc1));
    float l2 = acc2 - __bfloat162float(__float2bfloat16_rn(acc2));
    float l3 = acc3 - __bfloat162float(__float2bfloat16_rn(acc3));
    uint2 uh = make_uint2(pb2(acc0, acc1), pb2(acc2, acc3));
    uint2 ul = make_uint2(pb2(l0, l1), pb2(l2, l3));
    int g = lane >> 1;
    int didx = (n >> 7) * TILE_ELEMS + swz_idx(n & 127, g) + (lane & 1) * 4;
    *(uint2*)(g_sh + didx) = uh;
    *(uint2*)(g_sl + didx) = ul;
}

// ------------------------- readout -------------------------------------------
__device__ __forceinline__ unsigned enc_f(float f) {
    unsigned u = __float_as_uint(f);
    return (u & 0x80000000u) ? ~u : (u | 0x80000000u);
}

__global__ void readout_kernel(const int* __restrict__ batch) {
    int lane = threadIdx.x & 31;
    int n = (blockIdx.x * blockDim.x + threadIdx.x) >> 5;
    if (n >= NNODES) return;
    int g = __ldg(batch + n);
    float4 v = *(const float4*)(g_h + (size_t)n * HID + lane * 4);
    atomicAdd((float4*)(g_zsum + (size_t)g * HID) + lane, v);
    unsigned* mk = g_zmaxk + (size_t)g * HID + lane * 4;
    atomicMax(mk + 0, enc_f(v.x));
    atomicMax(mk + 1, enc_f(v.y));
    atomicMax(mk + 2, enc_f(v.z));
    atomicMax(mk + 3, enc_f(v.w));
    if (lane == 0) atomicAdd(&g_cnt[g], 1.f);
}

__global__ void final_kernel(const float* __restrict__ ro_w, const float* __restrict__ ro_b,
                             float* __restrict__ out)
{
    int gph = blockIdx.x;
    int j = threadIdx.x;
    __shared__ float smean[HID], smax[HID];
    float cntv = g_cnt[gph];
    float inv = 1.f / fmaxf(cntv, 1.f);
    bool has = cntv > 0.f;
    smean[j] = g_zsum[gph * HID + j] * inv;
    unsigned k = g_zmaxk[gph * HID + j];
    float mx = (k & 0x80000000u) ? __uint_as_float(k & 0x7fffffffu) : __uint_as_float(~k);
    smax[j] = has ? mx : 0.f;
    __syncthreads();
    float acc = ro_b[j];
#pragma unroll 4
    for (int kk = 0; kk < HID; kk++) {
        acc += smean[kk] * __ldg(ro_w + kk * HID + j);
        acc += smax[kk] * __ldg(ro_w + (HID + kk) * HID + j);
    }
    out[gph * HID + j] = fmaxf(acc, 0.f);
}

// ------------------------- launch --------------------------------------------
#define TG_DSMEM 196608

extern "C" void kernel_launch(void* const* d_in, const int* in_sizes, int n_in,
                              void* d_out, int out_size)
{
    const float* x     = (const float*)d_in[0];
    const int*   eidx  = (const int*)d_in[1];
    const float* eattr = (const float*)d_in[2];
    const int*   batch = (const int*)d_in[3];
    int base = (n_in == 21) ? 5 : 4;
    const float* lin_w = (const float*)d_in[base + 0];
    const float* lin_b = (const float*)d_in[base + 1];
    const float* mw1   = (const float*)d_in[base + 2];
    const float* mb1   = (const float*)d_in[base + 3];
    const float* mw2   = (const float*)d_in[base + 4];
    const float* mb2   = (const float*)d_in[base + 5];
    const float* bng   = (const float*)d_in[base + 6];
    const float* bnb   = (const float*)d_in[base + 7];
    const float* bnm   = (const float*)d_in[base + 8];
    const float* bnv   = (const float*)d_in[base + 9];
    const float* wih   = (const float*)d_in[base + 10];
    const float* whh   = (const float*)d_in[base + 11];
    const float* bih   = (const float*)d_in[base + 12];
    const float* bhh   = (const float*)d_in[base + 13];
    const float* ro_w  = (const float*)d_in[base + 14];
    const float* ro_b  = (const float*)d_in[base + 15];
    float* out = (float*)d_out;
    const int* src = eidx;
    const int* dst = eidx + NEDGES;

    float *hb, *pb, *ghb, *w2ib, *pkbias, *wihTb, *c2ib;
    __nv_bfloat16 *ahb, *alb, *shb, *slb;
    cudaGetSymbolAddress((void**)&hb, g_h);
    cudaGetSymbolAddress((void**)&pb, g_p);
    cudaGetSymbolAddress((void**)&ghb, g_gh);
    cudaGetSymbolAddress((void**)&w2ib, g_w2i);
    cudaGetSymbolAddress((void**)&pkbias, g_packbias);
    cudaGetSymbolAddress((void**)&wihTb, g_wihT);
    cudaGetSymbolAddress((void**)&ahb, g_ah);
    cudaGetSymbolAddress((void**)&alb, g_al);
    cudaGetSymbolAddress((void**)&shb, g_sh);
    cudaGetSymbolAddress((void**)&slb, g_sl);
    cudaGetSymbolAddress((void**)&c2ib, g_c2i);

    cudaFuncSetAttribute(tgemm, cudaFuncAttributeMaxDynamicSharedMemorySize, TG_DSMEM);
    cudaFuncSetAttribute(gigate, cudaFuncAttributeMaxDynamicSharedMemorySize, TG_DSMEM);

    int nblk1024 = (NNODES + 1023) / 1024;   // 49

    prep_kernel<<<(MTILES * 128 * 16 + 255) / 256, 256>>>(mw1, mb1, whh, bhh, wih, mb2, x);
    sgemm128<<<dim3(1, 3, NL), 256>>>(mw2, wihTb, 128, 384, w2ib,
                                      HID * HID, HID * 384, HID * 384);
    prep_convB<<<(NBTILES * 2048 + 255) / 256, 256>>>(lin_w);
    // launch 3: h = relu(x @ lin_w + b)     <-- ncu capture anchor
    tgemm<<<dim3(148, 1), 512, TG_DSMEM>>>(ahb, alb, 0,
                                           hb, 128, 1, nullptr, 0,
                                           lin_b, 1);
    csr_count<<<(NEDGES + 255) / 256, 256>>>(dst);
    csr_scan1<<<nblk1024, 1024>>>();
    csr_scan2<<<1, 64>>>(nblk1024);
    csr_final<<<(NNODES + 255) / 256, 256>>>();
    csr_fill<<<(NEDGES + 255) / 256, 256>>>(src, dst);
    conv_rows<<<(MTILES * 128 * 16 + 255) / 256, 256>>>(hb, ahb, alb);

    for (int l = 0; l < NL; l++) {
        // [P | GH] = h @ [W1a | whh^T] + [b1 | bhh]
        tgemm<<<dim3(37, 4), 512, TG_DSMEM>>>(ahb, alb, 1 + l * 4,
                                              pb, 128, 1, ghb, 384,
                                              pkbias + l * 512, 0);
        // S = segment_sum(relu(P[src] + ea@W1b)) -> bf16 tiles
        agg_kernel<<<(NNODES * 32 + 255) / 256, 256>>>(eattr,
                                                       mw1 + l * 144 * HID + 128 * HID);
        // fused: GI = S@W2i + deg*c2i + bih, then GRU gate + BN + residual
        gigate<<<dim3(148, 1), 512, TG_DSMEM>>>(shb, slb, 13 + l * 3,
                                                bih + l * 384, c2ib + l * 384,
                                                bng + l * HID, bnb + l * HID,
                                                bnm + l * HID, bnv + l * HID,
                                                (l < NL - 1) ? 1 : 0);
    }

    readout_kernel<<<(NNODES * 32 + 255) / 256, 256>>>(batch);
    final_kernel<<<NG, HID>>>(ro_w, ro_b, out);
    (void)in_sizes; (void)out_size;
}

// round 16
// speedup vs baseline: 1.0236x; 1.0236x over previous
#include <cuda_runtime.h>
#include <cuda_bf16.h>
#include <math.h>
#include <stdint.h>

#define NNODES 50000
#define NEDGES 800000
#define HID 128
#define EDIM 16
#define NL 3
#define NG 256
#define BN_EPS 1e-5f
#define MTILES 391            // ceil(50000/128)
#define TILE_ELEMS 16384      // 128x128
#define NBTILES 22            // 1 lin + 12 pack + 9 w2i
#define NPAD (MTILES * 128 - NNODES)   // 48 padding rows

// ------------------------- scratch (static device globals) -------------------
__device__ float g_h[NNODES * HID];
__device__ float g_p[NNODES * HID];
__device__ float g_gi[NNODES * 3 * HID];
__device__ float g_gh[NNODES * 3 * HID];
__device__ float g_deg[NNODES];
__device__ float g_w2i[NL * HID * 3 * HID];
__device__ float g_c2i[NL * 3 * HID];
__device__ float g_packb[NL * HID * 512];
__device__ float g_wihT[NL * HID * 384];
__device__ float g_packbias[NL * 512];
__device__ float g_zsum[NG * HID];
__device__ unsigned g_zmaxk[NG * HID];
__device__ float g_cnt[NG];
// CSR (dst-sorted edge list)
__device__ int g_cnt_i[NNODES];
__device__ int g_off[NNODES];
__device__ int g_cur[NNODES];
__device__ int g_blk[64];
__device__ int g_eid[NEDGES];
__device__ int g_esrc[NEDGES];
// bf16 split operand buffers (pre-swizzled tile layout)
__device__ __nv_bfloat16 g_ah[MTILES * TILE_ELEMS];
__device__ __nv_bfloat16 g_al[MTILES * TILE_ELEMS];
__device__ __nv_bfloat16 g_sh[MTILES * TILE_ELEMS];
__device__ __nv_bfloat16 g_sl[MTILES * TILE_ELEMS];
__device__ __nv_bfloat16 g_bh[NBTILES * TILE_ELEMS];
__device__ __nv_bfloat16 g_bl[NBTILES * TILE_ELEMS];

// ------------------------- helpers ------------------------------------------
__device__ __forceinline__ unsigned long long pk2(float lo, float hi) {
    unsigned long long r;
    asm("mov.b64 %0, {%1, %2};" : "=l"(r) : "f"(lo), "f"(hi));
    return r;
}
__device__ __forceinline__ void unpk2(unsigned long long v, float& lo, float& hi) {
    asm("mov.b64 {%0, %1}, %2;" : "=f"(lo), "=f"(hi) : "l"(v));
}
#define FMA2(acc, a, b) asm("fma.rn.f32x2 %0, %1, %2, %0;" : "+l"(acc) : "l"(a), "l"(b))
__device__ __forceinline__ float sigm(float x) { return 1.f / (1.f + __expf(-x)); }

__device__ __forceinline__ unsigned smem_u32(const void* p) {
    unsigned a;
    asm("{ .reg .u64 t; cvta.to.shared.u64 t, %1; cvt.u32.u64 %0, t; }" : "=r"(a) : "l"(p));
    return a;
}
__device__ __forceinline__ unsigned pb2(float a, float b) {
    __nv_bfloat162 t = __floats2bfloat162_rn(a, b);
    return *reinterpret_cast<unsigned*>(&t);
}
// swizzled 16B-granule index within a 128x128 bf16 tile
__device__ __forceinline__ int swz_g(int r, int c8) { return r * 16 + (c8 ^ (r & 7)); }
__device__ __forceinline__ int swz_idx(int r, int c8) { return swz_g(r, c8) * 8; }

__device__ __forceinline__ void split8(const float* o, uint4& uh, uint4& ul) {
    float lf[8];
#pragma unroll
    for (int i = 0; i < 8; i++)
        lf[i] = o[i] - __bfloat162float(__float2bfloat16_rn(o[i]));
    uh.x = pb2(o[0], o[1]); uh.y = pb2(o[2], o[3]);
    uh.z = pb2(o[4], o[5]); uh.w = pb2(o[6], o[7]);
    ul.x = pb2(lf[0], lf[1]); ul.y = pb2(lf[2], lf[3]);
    ul.z = pb2(lf[4], lf[5]); ul.w = pb2(lf[6], lf[7]);
}

#define LDSM4(r0, r1, r2, r3, addr) \
    asm volatile("ldmatrix.sync.aligned.m8n8.x4.shared.b16 {%0,%1,%2,%3}, [%4];" \
                 : "=r"(r0), "=r"(r1), "=r"(r2), "=r"(r3) : "r"(addr))

#define MMA16816(c, a0, a1, a2, a3, b0, b1) \
    asm volatile("mma.sync.aligned.m16n8k16.row.col.f32.bf16.bf16.f32 " \
                 "{%0,%1,%2,%3}, {%4,%5,%6,%7}, {%8,%9}, {%0,%1,%2,%3};" \
                 : "+f"((c)[0]), "+f"((c)[1]), "+f"((c)[2]), "+f"((c)[3]) \
                 : "r"(a0), "r"(a1), "r"(a2), "r"(a3), "r"(b0), "r"(b1))

#define CPA16(dst, src) \
    asm volatile("cp.async.cg.shared.global [%0], [%1], 16;" :: "r"(dst), "l"(src))
#define CPA_COMMIT() asm volatile("cp.async.commit_group;" ::: "memory")
#define CPA_WAIT0() asm volatile("cp.async.wait_group 0;" ::: "memory")

// ------------------------- tensor-core GEMM (mma.sync bf16) ------------------
// R8 shape: 512 threads = 16 warps (4x4); warp tile 32x32. Fused 3-term k-loop.
__global__ __launch_bounds__(512, 1) void tgemm(
    const __nv_bfloat16* __restrict__ Ahi, const __nv_bfloat16* __restrict__ Alo,
    int btile0,
    float* __restrict__ C0, int ld0, int ny0, float* __restrict__ C1, int ld1,
    const float* __restrict__ bias,
    const float* __restrict__ rowscale, const float* __restrict__ rowvec,
    int do_relu)
{
    extern __shared__ __align__(16) char rawsm[];
    unsigned ubase = smem_u32(rawsm);
    unsigned uAst[2] = {ubase, ubase + 65536};
    unsigned uBhi = ubase + 131072, uBlo = ubase + 163840;

    int tid = threadIdx.x;
    int warp = tid >> 5;
    int lane = tid & 31;
    int wm = warp & 3;
    int wn = warp >> 2;

    {
        int bt = btile0 + blockIdx.y;
        const uint4* gh4 = (const uint4*)(g_bh + (size_t)bt * TILE_ELEMS);
        const uint4* gl4 = (const uint4*)(g_bl + (size_t)bt * TILE_ELEMS);
#pragma unroll
        for (int i = tid; i < 2048; i += 512) {
            CPA16(uBhi + i * 16, gh4 + i);
            CPA16(uBlo + i * 16, gl4 + i);
        }
    }
    if ((int)blockIdx.x < MTILES) {
        const uint4* gh4 = (const uint4*)(Ahi + (size_t)blockIdx.x * TILE_ELEMS);
        const uint4* gl4 = (const uint4*)(Alo + (size_t)blockIdx.x * TILE_ELEMS);
#pragma unroll
        for (int i = tid; i < 2048; i += 512) {
            CPA16(uAst[0] + i * 16, gh4 + i);
            CPA16(uAst[0] + 32768 + i * 16, gl4 + i);
        }
    }
    CPA_COMMIT();

    float* Cp;
    int tcol, ldc;
    if ((int)blockIdx.y < ny0) { Cp = C0; tcol = blockIdx.y * 128; ldc = ld0; }
    else { Cp = C1; tcol = (blockIdx.y - ny0) * 128; ldc = ld1; }
    int gcb = blockIdx.y * 128;

    int a_r = wm * 32 + (lane & 7) + 8 * ((lane >> 3) & 1);
    int a_cg = lane >> 4;
    int b_r = wn * 32 + (lane & 7) + 8 * (lane >> 4);
    int b_cg = (lane >> 3) & 1;
    int t4 = lane >> 2;
    int t2 = (lane & 3) * 2;

    int stage = 0;
    for (int mt = blockIdx.x; mt < MTILES; mt += gridDim.x) {
        CPA_WAIT0();
        __syncthreads();

        int nxt = mt + gridDim.x;
        if (nxt < MTILES) {
            const uint4* gh4 = (const uint4*)(Ahi + (size_t)nxt * TILE_ELEMS);
            const uint4* gl4 = (const uint4*)(Alo + (size_t)nxt * TILE_ELEMS);
            unsigned ud = uAst[stage ^ 1];
#pragma unroll
            for (int i = tid; i < 2048; i += 512) {
                CPA16(ud + i * 16, gh4 + i);
                CPA16(ud + 32768 + i * 16, gl4 + i);
            }
        }
        CPA_COMMIT();

        float acc[2][4][4];
#pragma unroll
        for (int mi = 0; mi < 2; mi++)
#pragma unroll
            for (int ni = 0; ni < 4; ni++)
#pragma unroll
                for (int j = 0; j < 4; j++) acc[mi][ni][j] = 0.f;

        unsigned uAhi = uAst[stage], uAlo = uAst[stage] + 32768;
#pragma unroll
        for (int kc = 0; kc < 8; kc++) {
            unsigned ah[2][4], al[2][4], bh[2][4], bl[2][4];
#pragma unroll
            for (int mi = 0; mi < 2; mi++) {
                int soff = swz_g(a_r + mi * 16, kc * 2 + a_cg) * 16;
                LDSM4(ah[mi][0], ah[mi][1], ah[mi][2], ah[mi][3], uAhi + soff);
                LDSM4(al[mi][0], al[mi][1], al[mi][2], al[mi][3], uAlo + soff);
            }
#pragma unroll
            for (int nb = 0; nb < 2; nb++) {
                int soff = swz_g(b_r + nb * 16, kc * 2 + b_cg) * 16;
                LDSM4(bh[nb][0], bh[nb][1], bh[nb][2], bh[nb][3], uBhi + soff);
                LDSM4(bl[nb][0], bl[nb][1], bl[nb][2], bl[nb][3], uBlo + soff);
            }
#pragma unroll
            for (int mi = 0; mi < 2; mi++) {
#pragma unroll
                for (int ni = 0; ni < 4; ni++) {
                    int nb = ni >> 1;
                    int of = (ni & 1) * 2;
                    MMA16816(acc[mi][ni], ah[mi][0], ah[mi][1], ah[mi][2], ah[mi][3],
                             bh[nb][of], bh[nb][of + 1]);
                    MMA16816(acc[mi][ni], ah[mi][0], ah[mi][1], ah[mi][2], ah[mi][3],
                             bl[nb][of], bl[nb][of + 1]);
                    MMA16816(acc[mi][ni], al[mi][0], al[mi][1], al[mi][2], al[mi][3],
                             bh[nb][of], bh[nb][of + 1]);
                }
            }
        }

#pragma unroll
        for (int mi = 0; mi < 2; mi++) {
#pragma unroll
            for (int half = 0; half < 2; half++) {
                int r_in = wm * 32 + mi * 16 + t4 + half * 8;
                int grow = mt * 128 + r_in;
                if (grow >= NNODES) continue;
                float rs = rowscale ? rowscale[grow] : 0.f;
                float* cp = Cp + (size_t)grow * ldc + tcol;
#pragma unroll
                for (int ni = 0; ni < 4; ni++) {
                    int lc = wn * 32 + ni * 8 + t2;
                    float v0 = acc[mi][ni][half * 2 + 0] + bias[gcb + lc];
                    float v1 = acc[mi][ni][half * 2 + 1] + bias[gcb + lc + 1];
                    if (rowvec) {
                        v0 += rs * rowvec[gcb + lc];
                        v1 += rs * rowvec[gcb + lc + 1];
                    }
                    if (do_relu) { v0 = fmaxf(v0, 0.f); v1 = fmaxf(v1, 0.f); }
                    *(float2*)(cp + lc) = make_float2(v0, v1);
                }
            }
        }
        stage ^= 1;
    }
}

// ------------------------- fp32 sgemm (w2i prep only) ------------------------
#define BM 128
#define BN 128
#define BK 16
__device__ __forceinline__ int ASW(int k, int m) { return m ^ ((k * 8) & 127); }

__global__ __launch_bounds__(256, 2) void sgemm128(
    const float* __restrict__ A, const float* __restrict__ B,
    int M, int N, float* __restrict__ C0,
    int batchA, int batchB, int batchC)
{
    __shared__ unsigned long long As2[BK][BM];
    __shared__ float Bs[BK][BN];
    A += (size_t)blockIdx.z * batchA;
    B += (size_t)blockIdx.z * batchB;
    C0 += (size_t)blockIdx.z * batchC;
    int m0 = blockIdx.x * BM, n0 = blockIdx.y * BN;
    int t = threadIdx.x, rg = t >> 4, cg = t & 15;
    unsigned long long acc[8][4];
#pragma unroll
    for (int r = 0; r < 8; r++)
#pragma unroll
        for (int p = 0; p < 4; p++) acc[r][p] = 0ull;
#pragma unroll 1
    for (int k0 = 0; k0 < 128; k0 += BK) {
#pragma unroll
        for (int i = 0; i < 2; i++) {
            int id = t + i * 256, row = id >> 2, kk4 = (id & 3) * 4;
            float4 v = make_float4(0.f, 0.f, 0.f, 0.f);
            int gm = m0 + row;
            if (gm < M) v = *(const float4*)(A + (size_t)gm * 128 + k0 + kk4);
            As2[kk4 + 0][ASW(kk4 + 0, row)] = pk2(v.x, v.x);
            As2[kk4 + 1][ASW(kk4 + 1, row)] = pk2(v.y, v.y);
            As2[kk4 + 2][ASW(kk4 + 2, row)] = pk2(v.z, v.z);
            As2[kk4 + 3][ASW(kk4 + 3, row)] = pk2(v.w, v.w);
        }
#pragma unroll
        for (int i = 0; i < 2; i++) {
            int id = t + i * 256, row = id >> 5, nn = (id & 31) * 4;
            *(float4*)&Bs[row][nn] = *(const float4*)(B + (size_t)(k0 + row) * N + n0 + nn);
        }
        __syncthreads();
#pragma unroll
        for (int k = 0; k < BK; k++) {
            int ms = ASW(k, rg * 8);
            ulonglong2 a01 = *(const ulonglong2*)&As2[k][ms];
            ulonglong2 a23 = *(const ulonglong2*)&As2[k][ms + 2];
            ulonglong2 a45 = *(const ulonglong2*)&As2[k][ms + 4];
            ulonglong2 a67 = *(const ulonglong2*)&As2[k][ms + 6];
            ulonglong2 b01 = *(const ulonglong2*)&Bs[k][cg * 8];
            ulonglong2 b23 = *(const ulonglong2*)&Bs[k][cg * 8 + 4];
            unsigned long long av[8] = {a01.x, a01.y, a23.x, a23.y, a45.x, a45.y, a67.x, a67.y};
            unsigned long long bv[4] = {b01.x, b01.y, b23.x, b23.y};
#pragma unroll
            for (int r = 0; r < 8; r++)
#pragma unroll
                for (int p = 0; p < 4; p++) FMA2(acc[r][p], av[r], bv[p]);
        }
        __syncthreads();
    }
    int nbase = n0 + cg * 8;
#pragma unroll
    for (int r = 0; r < 8; r++) {
        int gm = m0 + rg * 8 + r;
        if (gm >= M) break;
        float c[8];
#pragma unroll
        for (int p = 0; p < 4; p++) unpk2(acc[r][p], c[2 * p], c[2 * p + 1]);
        *(float4*)(C0 + (size_t)gm * N + nbase) = make_float4(c[0], c[1], c[2], c[3]);
        *(float4*)(C0 + (size_t)gm * N + nbase + 4) = make_float4(c[4], c[5], c[6], c[7]);
    }
}

// ------------------------- prep kernel ---------------------------------------
__global__ void prep_kernel(const float* __restrict__ msg_w1, const float* __restrict__ msg_b1,
                            const float* __restrict__ whh, const float* __restrict__ bhh,
                            const float* __restrict__ wih, const float* __restrict__ msg_b2,
                            const float* __restrict__ x)
{
    int idx = blockIdx.x * blockDim.x + threadIdx.x;
    if (idx < NL * HID * 512) {
        int l = idx / (HID * 512);
        int r = idx % (HID * 512);
        int k = r / 512, c = r % 512;
        float v;
        if (c < HID) v = msg_w1[l * 144 * HID + k * HID + c];
        else v = whh[l * 384 * HID + (c - HID) * HID + k];
        g_packb[idx] = v;
    }
    if (idx < NL * HID * 384) {
        int l = idx / (HID * 384);
        int r = idx % (HID * 384);
        int o = r / 384, g = r % 384;
        g_wihT[idx] = wih[l * 384 * HID + g * HID + o];
    }
    if (idx < NL * 512) {
        int l = idx / 512, c = idx % 512;
        g_packbias[idx] = (c < HID) ? msg_b1[l * HID + c] : bhh[l * 384 + (c - HID)];
    }
    if (idx < NL * 384) {
        int l = idx / 384, g = idx % 384;
        const float* wr = wih + l * 384 * HID + g * HID;
        const float* b2 = msg_b2 + l * HID;
        float acc = 0.f;
#pragma unroll 8
        for (int j = 0; j < HID; j++) acc += b2[j] * __ldg(wr + j);
        g_c2i[idx] = acc;
    }
    if (idx < NNODES) g_cnt_i[idx] = 0;
    if (idx < NG * HID) { g_zsum[idx] = 0.f; g_zmaxk[idx] = 0u; }
    if (idx < NG) g_cnt[idx] = 0.f;
    if (idx < NPAD * 16) {
        int row = NNODES + idx / 16;
        int kg = idx % 16;
        int didx = (row >> 7) * TILE_ELEMS + swz_idx(row & 127, kg);
        uint4 z = make_uint4(0u, 0u, 0u, 0u);
        *(uint4*)(g_sh + didx) = z;
        *(uint4*)(g_sl + didx) = z;
    }
    if (idx < MTILES * 128 * 16) {
        int row = idx >> 4;
        int kg = idx & 15;
        float o[8];
        if (row < NNODES) {
            float4 a = *(const float4*)(x + (size_t)row * HID + kg * 8);
            float4 b = *(const float4*)(x + (size_t)row * HID + kg * 8 + 4);
            o[0] = a.x; o[1] = a.y; o[2] = a.z; o[3] = a.w;
            o[4] = b.x; o[5] = b.y; o[6] = b.z; o[7] = b.w;
        } else {
#pragma unroll
            for (int i = 0; i < 8; i++) o[i] = 0.f;
        }
        uint4 uh, ul;
        split8(o, uh, ul);
        int didx = (row >> 7) * TILE_ELEMS + swz_idx(row & 127, kg);
        *(uint4*)(g_ah + didx) = uh;
        *(uint4*)(g_al + didx) = ul;
    }
}

// convert all B weight tiles to swizzled bf16 hi/lo (tile layout [n][k])
__global__ void prep_convB(const float* __restrict__ lin_w) {
    int idx = blockIdx.x * blockDim.x + threadIdx.x;
    if (idx >= NBTILES * 2048) return;
    int tile = idx / 2048;
    int r = idx % 2048;
    int n_in = r >> 4;
    int kg = r & 15;
    float o[8];
#pragma unroll
    for (int i = 0; i < 8; i++) {
        int k = kg * 8 + i;
        float v;
        if (tile == 0) {
            v = lin_w[k * HID + n_in];
        } else if (tile < 13) {
            int l = (tile - 1) >> 2, j = (tile - 1) & 3;
            v = g_packb[l * (HID * 512) + k * 512 + j * 128 + n_in];
        } else {
            int l = (tile - 13) / 3, j = (tile - 13) % 3;
            v = g_w2i[(l * HID + k) * 384 + j * 128 + n_in];
        }
        o[i] = v;
    }
    uint4 uh, ul;
    split8(o, uh, ul);
    int didx = tile * TILE_ELEMS + swz_idx(n_in, kg);
    *(uint4*)(g_bh + didx) = uh;
    *(uint4*)(g_bl + didx) = ul;
}

// convert fp32 row-major [rows,128] -> swizzled bf16 hi/lo tiles (coalesced 16B)
__global__ void conv_rows(const float* __restrict__ src,
                          __nv_bfloat16* __restrict__ dhi, __nv_bfloat16* __restrict__ dlo)
{
    int idx = blockIdx.x * blockDim.x + threadIdx.x;
    if (idx >= MTILES * 128 * 16) return;
    int row = idx >> 4;
    int kg = idx & 15;
    float o[8];
    if (row < NNODES) {
        float4 a = *(const float4*)(src + (size_t)row * HID + kg * 8);
        float4 b = *(const float4*)(src + (size_t)row * HID + kg * 8 + 4);
        o[0] = a.x; o[1] = a.y; o[2] = a.z; o[3] = a.w;
        o[4] = b.x; o[5] = b.y; o[6] = b.z; o[7] = b.w;
    } else {
#pragma unroll
        for (int i = 0; i < 8; i++) o[i] = 0.f;
    }
    uint4 uh, ul;
    split8(o, uh, ul);
    int didx = (row >> 7) * TILE_ELEMS + swz_idx(row & 127, kg);
    *(uint4*)(dhi + didx) = uh;
    *(uint4*)(dlo + didx) = ul;
}

// ------------------------- CSR build -----------------------------------------
__global__ void csr_count(const int* __restrict__ dst) {
    int e = blockIdx.x * blockDim.x + threadIdx.x;
    if (e < NEDGES) atomicAdd(&g_cnt_i[dst[e]], 1);
}

__global__ __launch_bounds__(1024) void csr_scan1() {
    __shared__ int s[1024];
    int tid = threadIdx.x;
    int i = blockIdx.x * 1024 + tid;
    int c = (i < NNODES) ? g_cnt_i[i] : 0;
    s[tid] = c;
    __syncthreads();
#pragma unroll
    for (int off = 1; off < 1024; off <<= 1) {
        int v = (tid >= off) ? s[tid - off] : 0;
        __syncthreads();
        s[tid] += v;
        __syncthreads();
    }
    if (i < NNODES) g_off[i] = s[tid] - c;
    if (tid == 1023) g_blk[blockIdx.x] = s[1023];
}

// parallel 64-wide exclusive scan of block sums
__global__ void csr_scan2(int nblk) {
    __shared__ int s[64];
    int t = threadIdx.x;
    int v = (t < nblk) ? g_blk[t] : 0;
    s[t] = v;
    __syncthreads();
#pragma unroll
    for (int off = 1; off < 64; off <<= 1) {
        int u = (t >= off) ? s[t - off] : 0;
        __syncthreads();
        s[t] += u;
        __syncthreads();
    }
    if (t < nblk) g_blk[t] = s[t] - v;   // exclusive prefix
}

__global__ void csr_final() {
    int i = blockIdx.x * blockDim.x + threadIdx.x;
    if (i >= NNODES) return;
    int base = g_off[i] + g_blk[i >> 10];
    g_off[i] = base;
    g_cur[i] = base;
    g_deg[i] = (float)g_cnt_i[i];
}

__global__ void csr_fill(const int* __restrict__ src, const int* __restrict__ dst) {
    int e = blockIdx.x * blockDim.x + threadIdx.x;
    if (e >= NEDGES) return;
    int d = dst[e];
    int pos = atomicAdd(&g_cur[d], 1);
    g_eid[pos] = e;
    g_esrc[pos] = src[e];
}

// ------------------------- CSR gather-aggregate (R8 form) --------------------
__global__ __launch_bounds__(256) void agg_kernel(
    const float* __restrict__ ea, const float* __restrict__ w1b)
{
    int lane = threadIdx.x & 31;
    int n = (blockIdx.x * blockDim.x + threadIdx.x) >> 5;
    if (n >= NNODES) return;

    unsigned long long w0[16], w1[16];
#pragma unroll
    for (int t = 0; t < 16; t++) {
        float4 w = *(const float4*)(w1b + t * HID + lane * 4);
        w0[t] = pk2(w.x, w.y);
        w1[t] = pk2(w.z, w.w);
    }

    int base = g_off[n];
    int cnt = g_cnt_i[n];
    float acc0 = 0.f, acc1 = 0.f, acc2 = 0.f, acc3 = 0.f;

    for (int i = 0; i < cnt; i++) {
        int e = __ldg(g_eid + base + i);
        int s = __ldg(g_esrc + base + i);
        const float4* eap = (const float4*)(ea + (size_t)e * EDIM);
        float4 e0 = __ldg(eap + 0), e1 = __ldg(eap + 1);
        float4 e2 = __ldg(eap + 2), e3 = __ldg(eap + 3);
        ulonglong2 p2 = *(const ulonglong2*)(g_p + (size_t)s * HID + lane * 4);
        unsigned long long a0 = p2.x, a1 = p2.y;
        float ec[16] = {e0.x, e0.y, e0.z, e0.w, e1.x, e1.y, e1.z, e1.w,
                        e2.x, e2.y, e2.z, e2.w, e3.x, e3.y, e3.z, e3.w};
#pragma unroll
        for (int t = 0; t < 16; t++) {
            unsigned long long et = pk2(ec[t], ec[t]);
            FMA2(a0, w0[t], et);
            FMA2(a1, w1[t], et);
        }
        float x0, x1, x2, x3;
        unpk2(a0, x0, x1);
        unpk2(a1, x2, x3);
        acc0 += fmaxf(x0, 0.f);
        acc1 += fmaxf(x1, 0.f);
        acc2 += fmaxf(x2, 0.f);
        acc3 += fmaxf(x3, 0.f);
    }

    float l0 = acc0 - __bfloat162float(__float2bfloat16_rn(acc0));
    float l1 = acc1 - __bfloat162float(__float2bfloat16_rn(acc1));
    float l2 = acc2 - __bfloat162float(__float2bfloat16_rn(acc2));
    float l3 = acc3 - __bfloat162float(__float2bfloat16_rn(acc3));
    uint2 uh = make_uint2(pb2(acc0, acc1), pb2(acc2, acc3));
    uint2 ul = make_uint2(pb2(l0, l1), pb2(l2, l3));
    int g = lane >> 1;
    int didx = (n >> 7) * TILE_ELEMS + swz_idx(n & 127, g) + (lane & 1) * 4;
    *(uint2*)(g_sh + didx) = uh;
    *(uint2*)(g_sl + didx) = ul;
}

// ------------------------- GRU gates + BN + residual + bf16 out --------------
__global__ void gate_kernel(const float* __restrict__ gamma, const float* __restrict__ beta,
                            const float* __restrict__ mean, const float* __restrict__ var)
{
    int idx = blockIdx.x * blockDim.x + threadIdx.x;
    if (idx >= NNODES * 16) return;
    int n = idx >> 4;
    int q = idx & 15;
    int j0 = q * 8;
    const float* gi = g_gi + (size_t)n * 384 + j0;
    const float* gh = g_gh + (size_t)n * 384 + j0;
    float ir[8], iz[8], in_[8], hr[8], hz[8], hn[8], hv[8];
    *(float4*)(ir) = *(const float4*)(gi);         *(float4*)(ir + 4) = *(const float4*)(gi + 4);
    *(float4*)(iz) = *(const float4*)(gi + 128);   *(float4*)(iz + 4) = *(const float4*)(gi + 132);
    *(float4*)(in_) = *(const float4*)(gi + 256);  *(float4*)(in_ + 4) = *(const float4*)(gi + 260);
    *(float4*)(hr) = *(const float4*)(gh);         *(float4*)(hr + 4) = *(const float4*)(gh + 4);
    *(float4*)(hz) = *(const float4*)(gh + 128);   *(float4*)(hz + 4) = *(const float4*)(gh + 132);
    *(float4*)(hn) = *(const float4*)(gh + 256);   *(float4*)(hn + 4) = *(const float4*)(gh + 260);
    *(float4*)(hv) = *(const float4*)(g_h + (size_t)n * HID + j0);
    *(float4*)(hv + 4) = *(const float4*)(g_h + (size_t)n * HID + j0 + 4);
    float ov[8];
#pragma unroll
    for (int c = 0; c < 8; c++) {
        float r = sigm(ir[c] + hr[c]);
        float z = sigm(iz[c] + hz[c]);
        float nn = tanhf(in_[c] + r * hn[c]);
        float hnew = (1.f - z) * nn + z * hv[c];
        float bn = (hnew - mean[j0 + c]) * rsqrtf(var[j0 + c] + BN_EPS) * gamma[j0 + c]
                   + beta[j0 + c];
        ov[c] = hv[c] + bn;
    }
    *(float4*)(g_h + (size_t)n * HID + j0) = make_float4(ov[0], ov[1], ov[2], ov[3]);
    *(float4*)(g_h + (size_t)n * HID + j0 + 4) = make_float4(ov[4], ov[5], ov[6], ov[7]);
    uint4 uh, ul;
    split8(ov, uh, ul);
    int didx = (n >> 7) * TILE_ELEMS + swz_idx(n & 127, q);
    *(uint4*)(g_ah + didx) = uh;
    *(uint4*)(g_al + didx) = ul;
}

// ------------------------- readout -------------------------------------------
__device__ __forceinline__ unsigned enc_f(float f) {
    unsigned u = __float_as_uint(f);
    return (u & 0x80000000u) ? ~u : (u | 0x80000000u);
}

__global__ void readout_kernel(const int* __restrict__ batch) {
    int lane = threadIdx.x & 31;
    int n = (blockIdx.x * blockDim.x + threadIdx.x) >> 5;
    if (n >= NNODES) return;
    int g = __ldg(batch + n);
    float4 v = *(const float4*)(g_h + (size_t)n * HID + lane * 4);
    atomicAdd((float4*)(g_zsum + (size_t)g * HID) + lane, v);
    unsigned* mk = g_zmaxk + (size_t)g * HID + lane * 4;
    atomicMax(mk + 0, enc_f(v.x));
    atomicMax(mk + 1, enc_f(v.y));
    atomicMax(mk + 2, enc_f(v.z));
    atomicMax(mk + 3, enc_f(v.w));
    if (lane == 0) atomicAdd(&g_cnt[g], 1.f);
}

__global__ void final_kernel(const float* __restrict__ ro_w, const float* __restrict__ ro_b,
                             float* __restrict__ out)
{
    int gph = blockIdx.x;
    int j = threadIdx.x;
    __shared__ float smean[HID], smax[HID];
    float cntv = g_cnt[gph];
    float inv = 1.f / fmaxf(cntv, 1.f);
    bool has = cntv > 0.f;
    smean[j] = g_zsum[gph * HID + j] * inv;
    unsigned k = g_zmaxk[gph * HID + j];
    float mx = (k & 0x80000000u) ? __uint_as_float(k & 0x7fffffffu) : __uint_as_float(~k);
    smax[j] = has ? mx : 0.f;
    __syncthreads();
    float acc = ro_b[j];
#pragma unroll 4
    for (int kk = 0; kk < HID; kk++) {
        acc += smean[kk] * __ldg(ro_w + kk * HID + j);
        acc += smax[kk] * __ldg(ro_w + (HID + kk) * HID + j);
    }
    out[gph * HID + j] = fmaxf(acc, 0.f);
}

// ------------------------- launch --------------------------------------------
#define TG_DSMEM 196608

extern "C" void kernel_launch(void* const* d_in, const int* in_sizes, int n_in,
                              void* d_out, int out_size)
{
    const float* x     = (const float*)d_in[0];
    const int*   eidx  = (const int*)d_in[1];
    const float* eattr = (const float*)d_in[2];
    const int*   batch = (const int*)d_in[3];
    int base = (n_in == 21) ? 5 : 4;
    const float* lin_w = (const float*)d_in[base + 0];
    const float* lin_b = (const float*)d_in[base + 1];
    const float* mw1   = (const float*)d_in[base + 2];
    const float* mb1   = (const float*)d_in[base + 3];
    const float* mw2   = (const float*)d_in[base + 4];
    const float* mb2   = (const float*)d_in[base + 5];
    const float* bng   = (const float*)d_in[base + 6];
    const float* bnb   = (const float*)d_in[base + 7];
    const float* bnm   = (const float*)d_in[base + 8];
    const float* bnv   = (const float*)d_in[base + 9];
    const float* wih   = (const float*)d_in[base + 10];
    const float* whh   = (const float*)d_in[base + 11];
    const float* bih   = (const float*)d_in[base + 12];
    const float* bhh   = (const float*)d_in[base + 13];
    const float* ro_w  = (const float*)d_in[base + 14];
    const float* ro_b  = (const float*)d_in[base + 15];
    float* out = (float*)d_out;
    const int* src = eidx;
    const int* dst = eidx + NEDGES;

    float *hb, *pb, *gib, *ghb, *degb, *w2ib, *pkbias, *wihTb, *c2ib;
    __nv_bfloat16 *ahb, *alb, *shb, *slb;
    cudaGetSymbolAddress((void**)&hb, g_h);
    cudaGetSymbolAddress((void**)&pb, g_p);
    cudaGetSymbolAddress((void**)&gib, g_gi);
    cudaGetSymbolAddress((void**)&ghb, g_gh);
    cudaGetSymbolAddress((void**)&degb, g_deg);
    cudaGetSymbolAddress((void**)&w2ib, g_w2i);
    cudaGetSymbolAddress((void**)&pkbias, g_packbias);
    cudaGetSymbolAddress((void**)&wihTb, g_wihT);
    cudaGetSymbolAddress((void**)&ahb, g_ah);
    cudaGetSymbolAddress((void**)&alb, g_al);
    cudaGetSymbolAddress((void**)&shb, g_sh);
    cudaGetSymbolAddress((void**)&slb, g_sl);
    cudaGetSymbolAddress((void**)&c2ib, g_c2i);

    cudaFuncSetAttribute(tgemm, cudaFuncAttributeMaxDynamicSharedMemorySize, TG_DSMEM);

    int nblk1024 = (NNODES + 1023) / 1024;   // 49

    prep_kernel<<<(MTILES * 128 * 16 + 255) / 256, 256>>>(mw1, mb1, whh, bhh, wih, mb2, x);
    sgemm128<<<dim3(1, 3, NL), 256>>>(mw2, wihTb, 128, 384, w2ib,
                                      HID * HID, HID * 384, HID * 384);
    prep_convB<<<(NBTILES * 2048 + 255) / 256, 256>>>(lin_w);
    // launch 3: h = relu(x @ lin_w + b)     <-- ncu capture anchor
    tgemm<<<dim3(148, 1), 512, TG_DSMEM>>>(ahb, alb, 0,
                                           hb, 128, 1, nullptr, 0,
                                           lin_b, nullptr, nullptr, 1);
    csr_count<<<(NEDGES + 255) / 256, 256>>>(dst);
    csr_scan1<<<nblk1024, 1024>>>();
    csr_scan2<<<1, 64>>>(nblk1024);
    csr_final<<<(NNODES + 255) / 256, 256>>>();
    csr_fill<<<(NEDGES + 255) / 256, 256>>>(src, dst);
    conv_rows<<<(MTILES * 128 * 16 + 255) / 256, 256>>>(hb, ahb, alb);

    for (int l = 0; l < NL; l++) {
        tgemm<<<dim3(37, 4), 512, TG_DSMEM>>>(ahb, alb, 1 + l * 4,
                                              pb, 128, 1, ghb, 384,
                                              pkbias + l * 512, nullptr, nullptr, 0);
        agg_kernel<<<(NNODES * 32 + 255) / 256, 256>>>(eattr,
                                                       mw1 + l * 144 * HID + 128 * HID);
        tgemm<<<dim3(49, 3), 512, TG_DSMEM>>>(shb, slb, 13 + l * 3,
                                              gib, 384, 3, nullptr, 0,
                                              bih + l * 384, degb, c2ib + l * 384, 0);
        gate_kernel<<<(NNODES * 16 + 255) / 256, 256>>>(bng + l * HID, bnb + l * HID,
                                                        bnm + l * HID, bnv + l * HID);
    }

    readout_kernel<<<(NNODES * 32 + 255) / 256, 256>>>(batch);
    final_kernel<<<NG, HID>>>(ro_w, ro_b, out);
    (void)in_sizes; (void)out_size;
}

// round 17
// speedup vs baseline: 1.0330x; 1.0092x over previous
#include <cuda_runtime.h>
#include <cuda_bf16.h>
#include <math.h>
#include <stdint.h>

#define NNODES 50000
#define NEDGES 800000
#define HID 128
#define EDIM 16
#define NL 3
#define NG 256
#define BN_EPS 1e-5f
#define MTILES 391            // ceil(50000/128)
#define TILE_ELEMS 16384      // 128x128
#define NBTILES 22            // 1 lin + 12 pack + 9 w2i
#define NPAD (MTILES * 128 - NNODES)   // 48 padding rows

// ------------------------- scratch (static device globals) -------------------
__device__ float g_h[NNODES * HID];
__device__ float g_p[NNODES * HID];
__device__ float g_gi[NNODES * 3 * HID];
__device__ float g_gh[NNODES * 3 * HID];
__device__ float g_deg[NNODES];
__device__ float g_w2i[NL * HID * 3 * HID];
__device__ float g_c2i[NL * 3 * HID];
__device__ float g_packb[NL * HID * 512];
__device__ float g_wihT[NL * HID * 384];
__device__ float g_packbias[NL * 512];
__device__ float g_zsum[NG * HID];
__device__ unsigned g_zmaxk[NG * HID];
__device__ float g_cnt[NG];
// CSR (dst-sorted edge list)
__device__ int g_cnt_i[NNODES];
__device__ int g_off[NNODES];
__device__ int g_cur[NNODES];
__device__ int g_blk[64];
__device__ int g_eid[NEDGES];
__device__ int g_esrc[NEDGES];
// bf16 split operand buffers (pre-swizzled tile layout)
__device__ __nv_bfloat16 g_ah[MTILES * TILE_ELEMS];
__device__ __nv_bfloat16 g_al[MTILES * TILE_ELEMS];
__device__ __nv_bfloat16 g_sh[MTILES * TILE_ELEMS];
__device__ __nv_bfloat16 g_sl[MTILES * TILE_ELEMS];
__device__ __nv_bfloat16 g_bh[NBTILES * TILE_ELEMS];
__device__ __nv_bfloat16 g_bl[NBTILES * TILE_ELEMS];

// ------------------------- helpers ------------------------------------------
__device__ __forceinline__ unsigned long long pk2(float lo, float hi) {
    unsigned long long r;
    asm("mov.b64 %0, {%1, %2};" : "=l"(r) : "f"(lo), "f"(hi));
    return r;
}
__device__ __forceinline__ void unpk2(unsigned long long v, float& lo, float& hi) {
    asm("mov.b64 {%0, %1}, %2;" : "=f"(lo), "=f"(hi) : "l"(v));
}
#define FMA2(acc, a, b) asm("fma.rn.f32x2 %0, %1, %2, %0;" : "+l"(acc) : "l"(a), "l"(b))
__device__ __forceinline__ float sigm(float x) { return 1.f / (1.f + __expf(-x)); }

__device__ __forceinline__ unsigned smem_u32(const void* p) {
    unsigned a;
    asm("{ .reg .u64 t; cvta.to.shared.u64 t, %1; cvt.u32.u64 %0, t; }" : "=r"(a) : "l"(p));
    return a;
}
__device__ __forceinline__ unsigned pb2(float a, float b) {
    __nv_bfloat162 t = __floats2bfloat162_rn(a, b);
    return *reinterpret_cast<unsigned*>(&t);
}
// swizzled 16B-granule index within a 128x128 bf16 tile
__device__ __forceinline__ int swz_g(int r, int c8) { return r * 16 + (c8 ^ (r & 7)); }
__device__ __forceinline__ int swz_idx(int r, int c8) { return swz_g(r, c8) * 8; }

__device__ __forceinline__ void split8(const float* o, uint4& uh, uint4& ul) {
    float lf[8];
#pragma unroll
    for (int i = 0; i < 8; i++)
        lf[i] = o[i] - __bfloat162float(__float2bfloat16_rn(o[i]));
    uh.x = pb2(o[0], o[1]); uh.y = pb2(o[2], o[3]);
    uh.z = pb2(o[4], o[5]); uh.w = pb2(o[6], o[7]);
    ul.x = pb2(lf[0], lf[1]); ul.y = pb2(lf[2], lf[3]);
    ul.z = pb2(lf[4], lf[5]); ul.w = pb2(lf[6], lf[7]);
}

#define LDSM4(r0, r1, r2, r3, addr) \
    asm volatile("ldmatrix.sync.aligned.m8n8.x4.shared.b16 {%0,%1,%2,%3}, [%4];" \
                 : "=r"(r0), "=r"(r1), "=r"(r2), "=r"(r3) : "r"(addr))

#define MMA16816(c, a0, a1, a2, a3, b0, b1) \
    asm volatile("mma.sync.aligned.m16n8k16.row.col.f32.bf16.bf16.f32 " \
                 "{%0,%1,%2,%3}, {%4,%5,%6,%7}, {%8,%9}, {%0,%1,%2,%3};" \
                 : "+f"((c)[0]), "+f"((c)[1]), "+f"((c)[2]), "+f"((c)[3]) \
                 : "r"(a0), "r"(a1), "r"(a2), "r"(a3), "r"(b0), "r"(b1))

#define CPA16(dst, src) \
    asm volatile("cp.async.cg.shared.global [%0], [%1], 16;" :: "r"(dst), "l"(src))
#define CPA_COMMIT() asm volatile("cp.async.commit_group;" ::: "memory")
#define CPA_WAIT0() asm volatile("cp.async.wait_group 0;" ::: "memory")

// ------------------------- tensor-core GEMM (mma.sync bf16) ------------------
// R8 shape: 512 threads = 16 warps (4x4); warp tile 32x32. Fused 3-term k-loop.
__global__ __launch_bounds__(512, 1) void tgemm(
    const __nv_bfloat16* __restrict__ Ahi, const __nv_bfloat16* __restrict__ Alo,
    int btile0,
    float* __restrict__ C0, int ld0, int ny0, float* __restrict__ C1, int ld1,
    const float* __restrict__ bias,
    const float* __restrict__ rowscale, const float* __restrict__ rowvec,
    int do_relu)
{
    extern __shared__ __align__(16) char rawsm[];
    unsigned ubase = smem_u32(rawsm);
    unsigned uAst[2] = {ubase, ubase + 65536};
    unsigned uBhi = ubase + 131072, uBlo = ubase + 163840;

    int tid = threadIdx.x;
    int warp = tid >> 5;
    int lane = tid & 31;
    int wm = warp & 3;
    int wn = warp >> 2;

    {
        int bt = btile0 + blockIdx.y;
        const uint4* gh4 = (const uint4*)(g_bh + (size_t)bt * TILE_ELEMS);
        const uint4* gl4 = (const uint4*)(g_bl + (size_t)bt * TILE_ELEMS);
#pragma unroll
        for (int i = tid; i < 2048; i += 512) {
            CPA16(uBhi + i * 16, gh4 + i);
            CPA16(uBlo + i * 16, gl4 + i);
        }
    }
    if ((int)blockIdx.x < MTILES) {
        const uint4* gh4 = (const uint4*)(Ahi + (size_t)blockIdx.x * TILE_ELEMS);
        const uint4* gl4 = (const uint4*)(Alo + (size_t)blockIdx.x * TILE_ELEMS);
#pragma unroll
        for (int i = tid; i < 2048; i += 512) {
            CPA16(uAst[0] + i * 16, gh4 + i);
            CPA16(uAst[0] + 32768 + i * 16, gl4 + i);
        }
    }
    CPA_COMMIT();

    float* Cp;
    int tcol, ldc;
    if ((int)blockIdx.y < ny0) { Cp = C0; tcol = blockIdx.y * 128; ldc = ld0; }
    else { Cp = C1; tcol = (blockIdx.y - ny0) * 128; ldc = ld1; }
    int gcb = blockIdx.y * 128;

    int a_r = wm * 32 + (lane & 7) + 8 * ((lane >> 3) & 1);
    int a_cg = lane >> 4;
    int b_r = wn * 32 + (lane & 7) + 8 * (lane >> 4);
    int b_cg = (lane >> 3) & 1;
    int t4 = lane >> 2;
    int t2 = (lane & 3) * 2;

    int stage = 0;
    for (int mt = blockIdx.x; mt < MTILES; mt += gridDim.x) {
        CPA_WAIT0();
        __syncthreads();

        int nxt = mt + gridDim.x;
        if (nxt < MTILES) {
            const uint4* gh4 = (const uint4*)(Ahi + (size_t)nxt * TILE_ELEMS);
            const uint4* gl4 = (const uint4*)(Alo + (size_t)nxt * TILE_ELEMS);
            unsigned ud = uAst[stage ^ 1];
#pragma unroll
            for (int i = tid; i < 2048; i += 512) {
                CPA16(ud + i * 16, gh4 + i);
                CPA16(ud + 32768 + i * 16, gl4 + i);
            }
        }
        CPA_COMMIT();

        float acc[2][4][4];
#pragma unroll
        for (int mi = 0; mi < 2; mi++)
#pragma unroll
            for (int ni = 0; ni < 4; ni++)
#pragma unroll
                for (int j = 0; j < 4; j++) acc[mi][ni][j] = 0.f;

        unsigned uAhi = uAst[stage], uAlo = uAst[stage] + 32768;
#pragma unroll
        for (int kc = 0; kc < 8; kc++) {
            unsigned ah[2][4], al[2][4], bh[2][4], bl[2][4];
#pragma unroll
            for (int mi = 0; mi < 2; mi++) {
                int soff = swz_g(a_r + mi * 16, kc * 2 + a_cg) * 16;
                LDSM4(ah[mi][0], ah[mi][1], ah[mi][2], ah[mi][3], uAhi + soff);
                LDSM4(al[mi][0], al[mi][1], al[mi][2], al[mi][3], uAlo + soff);
            }
#pragma unroll
            for (int nb = 0; nb < 2; nb++) {
                int soff = swz_g(b_r + nb * 16, kc * 2 + b_cg) * 16;
                LDSM4(bh[nb][0], bh[nb][1], bh[nb][2], bh[nb][3], uBhi + soff);
                LDSM4(bl[nb][0], bl[nb][1], bl[nb][2], bl[nb][3], uBlo + soff);
            }
#pragma unroll
            for (int mi = 0; mi < 2; mi++) {
#pragma unroll
                for (int ni = 0; ni < 4; ni++) {
                    int nb = ni >> 1;
                    int of = (ni & 1) * 2;
                    MMA16816(acc[mi][ni], ah[mi][0], ah[mi][1], ah[mi][2], ah[mi][3],
                             bh[nb][of], bh[nb][of + 1]);
                    MMA16816(acc[mi][ni], ah[mi][0], ah[mi][1], ah[mi][2], ah[mi][3],
                             bl[nb][of], bl[nb][of + 1]);
                    MMA16816(acc[mi][ni], al[mi][0], al[mi][1], al[mi][2], al[mi][3],
                             bh[nb][of], bh[nb][of + 1]);
                }
            }
        }

#pragma unroll
        for (int mi = 0; mi < 2; mi++) {
#pragma unroll
            for (int half = 0; half < 2; half++) {
                int r_in = wm * 32 + mi * 16 + t4 + half * 8;
                int grow = mt * 128 + r_in;
                if (grow >= NNODES) continue;
                float rs = rowscale ? rowscale[grow] : 0.f;
                float* cp = Cp + (size_t)grow * ldc + tcol;
#pragma unroll
                for (int ni = 0; ni < 4; ni++) {
                    int lc = wn * 32 + ni * 8 + t2;
                    float v0 = acc[mi][ni][half * 2 + 0] + bias[gcb + lc];
                    float v1 = acc[mi][ni][half * 2 + 1] + bias[gcb + lc + 1];
                    if (rowvec) {
                        v0 += rs * rowvec[gcb + lc];
                        v1 += rs * rowvec[gcb + lc + 1];
                    }
                    if (do_relu) { v0 = fmaxf(v0, 0.f); v1 = fmaxf(v1, 0.f); }
                    *(float2*)(cp + lc) = make_float2(v0, v1);
                }
            }
        }
        stage ^= 1;
    }
}

// ------------------------- fp32 sgemm (w2i prep only) ------------------------
#define BM 128
#define BN 128
#define BK 16
__device__ __forceinline__ int ASW(int k, int m) { return m ^ ((k * 8) & 127); }

__global__ __launch_bounds__(256, 2) void sgemm128(
    const float* __restrict__ A, const float* __restrict__ B,
    int M, int N, float* __restrict__ C0,
    int batchA, int batchB, int batchC)
{
    __shared__ unsigned long long As2[BK][BM];
    __shared__ float Bs[BK][BN];
    A += (size_t)blockIdx.z * batchA;
    B += (size_t)blockIdx.z * batchB;
    C0 += (size_t)blockIdx.z * batchC;
    int m0 = blockIdx.x * BM, n0 = blockIdx.y * BN;
    int t = threadIdx.x, rg = t >> 4, cg = t & 15;
    unsigned long long acc[8][4];
#pragma unroll
    for (int r = 0; r < 8; r++)
#pragma unroll
        for (int p = 0; p < 4; p++) acc[r][p] = 0ull;
#pragma unroll 1
    for (int k0 = 0; k0 < 128; k0 += BK) {
#pragma unroll
        for (int i = 0; i < 2; i++) {
            int id = t + i * 256, row = id >> 2, kk4 = (id & 3) * 4;
            float4 v = make_float4(0.f, 0.f, 0.f, 0.f);
            int gm = m0 + row;
            if (gm < M) v = *(const float4*)(A + (size_t)gm * 128 + k0 + kk4);
            As2[kk4 + 0][ASW(kk4 + 0, row)] = pk2(v.x, v.x);
            As2[kk4 + 1][ASW(kk4 + 1, row)] = pk2(v.y, v.y);
            As2[kk4 + 2][ASW(kk4 + 2, row)] = pk2(v.z, v.z);
            As2[kk4 + 3][ASW(kk4 + 3, row)] = pk2(v.w, v.w);
        }
#pragma unroll
        for (int i = 0; i < 2; i++) {
            int id = t + i * 256, row = id >> 5, nn = (id & 31) * 4;
            *(float4*)&Bs[row][nn] = *(const float4*)(B + (size_t)(k0 + row) * N + n0 + nn);
        }
        __syncthreads();
#pragma unroll
        for (int k = 0; k < BK; k++) {
            int ms = ASW(k, rg * 8);
            ulonglong2 a01 = *(const ulonglong2*)&As2[k][ms];
            ulonglong2 a23 = *(const ulonglong2*)&As2[k][ms + 2];
            ulonglong2 a45 = *(const ulonglong2*)&As2[k][ms + 4];
            ulonglong2 a67 = *(const ulonglong2*)&As2[k][ms + 6];
            ulonglong2 b01 = *(const ulonglong2*)&Bs[k][cg * 8];
            ulonglong2 b23 = *(const ulonglong2*)&Bs[k][cg * 8 + 4];
            unsigned long long av[8] = {a01.x, a01.y, a23.x, a23.y, a45.x, a45.y, a67.x, a67.y};
            unsigned long long bv[4] = {b01.x, b01.y, b23.x, b23.y};
#pragma unroll
            for (int r = 0; r < 8; r++)
#pragma unroll
                for (int p = 0; p < 4; p++) FMA2(acc[r][p], av[r], bv[p]);
        }
        __syncthreads();
    }
    int nbase = n0 + cg * 8;
#pragma unroll
    for (int r = 0; r < 8; r++) {
        int gm = m0 + rg * 8 + r;
        if (gm >= M) break;
        float c[8];
#pragma unroll
        for (int p = 0; p < 4; p++) unpk2(acc[r][p], c[2 * p], c[2 * p + 1]);
        *(float4*)(C0 + (size_t)gm * N + nbase) = make_float4(c[0], c[1], c[2], c[3]);
        *(float4*)(C0 + (size_t)gm * N + nbase + 4) = make_float4(c[4], c[5], c[6], c[7]);
    }
}

// ------------------------- prep kernel (NO g_cnt_i zero; that moved to s2) ---
__global__ void prep_kernel(const float* __restrict__ msg_w1, const float* __restrict__ msg_b1,
                            const float* __restrict__ whh, const float* __restrict__ bhh,
                            const float* __restrict__ wih, const float* __restrict__ msg_b2,
                            const float* __restrict__ x)
{
    int idx = blockIdx.x * blockDim.x + threadIdx.x;
    if (idx < NL * HID * 512) {
        int l = idx / (HID * 512);
        int r = idx % (HID * 512);
        int k = r / 512, c = r % 512;
        float v;
        if (c < HID) v = msg_w1[l * 144 * HID + k * HID + c];
        else v = whh[l * 384 * HID + (c - HID) * HID + k];
        g_packb[idx] = v;
    }
    if (idx < NL * HID * 384) {
        int l = idx / (HID * 384);
        int r = idx % (HID * 384);
        int o = r / 384, g = r % 384;
        g_wihT[idx] = wih[l * 384 * HID + g * HID + o];
    }
    if (idx < NL * 512) {
        int l = idx / 512, c = idx % 512;
        g_packbias[idx] = (c < HID) ? msg_b1[l * HID + c] : bhh[l * 384 + (c - HID)];
    }
    if (idx < NL * 384) {
        int l = idx / 384, g = idx % 384;
        const float* wr = wih + l * 384 * HID + g * HID;
        const float* b2 = msg_b2 + l * HID;
        float acc = 0.f;
#pragma unroll 8
        for (int j = 0; j < HID; j++) acc += b2[j] * __ldg(wr + j);
        g_c2i[idx] = acc;
    }
    if (idx < NG * HID) { g_zsum[idx] = 0.f; g_zmaxk[idx] = 0u; }
    if (idx < NG) g_cnt[idx] = 0.f;
    if (idx < NPAD * 16) {
        int row = NNODES + idx / 16;
        int kg = idx % 16;
        int didx = (row >> 7) * TILE_ELEMS + swz_idx(row & 127, kg);
        uint4 z = make_uint4(0u, 0u, 0u, 0u);
        *(uint4*)(g_sh + didx) = z;
        *(uint4*)(g_sl + didx) = z;
    }
    if (idx < MTILES * 128 * 16) {
        int row = idx >> 4;
        int kg = idx & 15;
        float o[8];
        if (row < NNODES) {
            float4 a = *(const float4*)(x + (size_t)row * HID + kg * 8);
            float4 b = *(const float4*)(x + (size_t)row * HID + kg * 8 + 4);
            o[0] = a.x; o[1] = a.y; o[2] = a.z; o[3] = a.w;
            o[4] = b.x; o[5] = b.y; o[6] = b.z; o[7] = b.w;
        } else {
#pragma unroll
            for (int i = 0; i < 8; i++) o[i] = 0.f;
        }
        uint4 uh, ul;
        split8(o, uh, ul);
        int didx = (row >> 7) * TILE_ELEMS + swz_idx(row & 127, kg);
        *(uint4*)(g_ah + didx) = uh;
        *(uint4*)(g_al + didx) = ul;
    }
}

// convert all B weight tiles to swizzled bf16 hi/lo (tile layout [n][k])
__global__ void prep_convB(const float* __restrict__ lin_w) {
    int idx = blockIdx.x * blockDim.x + threadIdx.x;
    if (idx >= NBTILES * 2048) return;
    int tile = idx / 2048;
    int r = idx % 2048;
    int n_in = r >> 4;
    int kg = r & 15;
    float o[8];
#pragma unroll
    for (int i = 0; i < 8; i++) {
        int k = kg * 8 + i;
        float v;
        if (tile == 0) {
            v = lin_w[k * HID + n_in];
        } else if (tile < 13) {
            int l = (tile - 1) >> 2, j = (tile - 1) & 3;
            v = g_packb[l * (HID * 512) + k * 512 + j * 128 + n_in];
        } else {
            int l = (tile - 13) / 3, j = (tile - 13) % 3;
            v = g_w2i[(l * HID + k) * 384 + j * 128 + n_in];
        }
        o[i] = v;
    }
    uint4 uh, ul;
    split8(o, uh, ul);
    int didx = tile * TILE_ELEMS + swz_idx(n_in, kg);
    *(uint4*)(g_bh + didx) = uh;
    *(uint4*)(g_bl + didx) = ul;
}

// convert fp32 row-major [rows,128] -> swizzled bf16 hi/lo tiles (coalesced 16B)
__global__ void conv_rows(const float* __restrict__ src,
                          __nv_bfloat16* __restrict__ dhi, __nv_bfloat16* __restrict__ dlo)
{
    int idx = blockIdx.x * blockDim.x + threadIdx.x;
    if (idx >= MTILES * 128 * 16) return;
    int row = idx >> 4;
    int kg = idx & 15;
    float o[8];
    if (row < NNODES) {
        float4 a = *(const float4*)(src + (size_t)row * HID + kg * 8);
        float4 b = *(const float4*)(src + (size_t)row * HID + kg * 8 + 4);
        o[0] = a.x; o[1] = a.y; o[2] = a.z; o[3] = a.w;
        o[4] = b.x; o[5] = b.y; o[6] = b.z; o[7] = b.w;
    } else {
#pragma unroll
        for (int i = 0; i < 8; i++) o[i] = 0.f;
    }
    uint4 uh, ul;
    split8(o, uh, ul);
    int didx = (row >> 7) * TILE_ELEMS + swz_idx(row & 127, kg);
    *(uint4*)(dhi + didx) = uh;
    *(uint4*)(dlo + didx) = ul;
}

// ------------------------- CSR build (side-stream chain) ---------------------
__global__ void csr_zero() {
    int i = blockIdx.x * blockDim.x + threadIdx.x;
    if (i < NNODES) g_cnt_i[i] = 0;
}

__global__ void csr_count(const int* __restrict__ dst) {
    int e = blockIdx.x * blockDim.x + threadIdx.x;
    if (e < NEDGES) atomicAdd(&g_cnt_i[dst[e]], 1);
}

__global__ __launch_bounds__(1024) void csr_scan1() {
    __shared__ int s[1024];
    int tid = threadIdx.x;
    int i = blockIdx.x * 1024 + tid;
    int c = (i < NNODES) ? g_cnt_i[i] : 0;
    s[tid] = c;
    __syncthreads();
#pragma unroll
    for (int off = 1; off < 1024; off <<= 1) {
        int v = (tid >= off) ? s[tid - off] : 0;
        __syncthreads();
        s[tid] += v;
        __syncthreads();
    }
    if (i < NNODES) g_off[i] = s[tid] - c;
    if (tid == 1023) g_blk[blockIdx.x] = s[1023];
}

__global__ void csr_scan2(int nblk) {
    __shared__ int s[64];
    int t = threadIdx.x;
    int v = (t < nblk) ? g_blk[t] : 0;
    s[t] = v;
    __syncthreads();
#pragma unroll
    for (int off = 1; off < 64; off <<= 1) {
        int u = (t >= off) ? s[t - off] : 0;
        __syncthreads();
        s[t] += u;
        __syncthreads();
    }
    if (t < nblk) g_blk[t] = s[t] - v;   // exclusive prefix
}

__global__ void csr_final() {
    int i = blockIdx.x * blockDim.x + threadIdx.x;
    if (i >= NNODES) return;
    int base = g_off[i] + g_blk[i >> 10];
    g_off[i] = base;
    g_cur[i] = base;
    g_deg[i] = (float)g_cnt_i[i];
}

__global__ void csr_fill(const int* __restrict__ src, const int* __restrict__ dst) {
    int e = blockIdx.x * blockDim.x + threadIdx.x;
    if (e >= NEDGES) return;
    int d = dst[e];
    int pos = atomicAdd(&g_cur[d], 1);
    g_eid[pos] = e;
    g_esrc[pos] = src[e];
}

// ------------------------- CSR gather-aggregate (R8 form) --------------------
__global__ __launch_bounds__(256) void agg_kernel(
    const float* __restrict__ ea, const float* __restrict__ w1b)
{
    int lane = threadIdx.x & 31;
    int n = (blockIdx.x * blockDim.x + threadIdx.x) >> 5;
    if (n >= NNODES) return;

    unsigned long long w0[16], w1[16];
#pragma unroll
    for (int t = 0; t < 16; t++) {
        float4 w = *(const float4*)(w1b + t * HID + lane * 4);
        w0[t] = pk2(w.x, w.y);
        w1[t] = pk2(w.z, w.w);
    }

    int base = g_off[n];
    int cnt = g_cnt_i[n];
    float acc0 = 0.f, acc1 = 0.f, acc2 = 0.f, acc3 = 0.f;

    for (int i = 0; i < cnt; i++) {
        int e = __ldg(g_eid + base + i);
        int s = __ldg(g_esrc + base + i);
        const float4* eap = (const float4*)(ea + (size_t)e * EDIM);
        float4 e0 = __ldg(eap + 0), e1 = __ldg(eap + 1);
        float4 e2 = __ldg(eap + 2), e3 = __ldg(eap + 3);
        ulonglong2 p2 = *(const ulonglong2*)(g_p + (size_t)s * HID + lane * 4);
        unsigned long long a0 = p2.x, a1 = p2.y;
        float ec[16] = {e0.x, e0.y, e0.z, e0.w, e1.x, e1.y, e1.z, e1.w,
                        e2.x, e2.y, e2.z, e2.w, e3.x, e3.y, e3.z, e3.w};
#pragma unroll
        for (int t = 0; t < 16; t++) {
            unsigned long long et = pk2(ec[t], ec[t]);
            FMA2(a0, w0[t], et);
            FMA2(a1, w1[t], et);
        }
        float x0, x1, x2, x3;
        unpk2(a0, x0, x1);
        unpk2(a1, x2, x3);
        acc0 += fmaxf(x0, 0.f);
        acc1 += fmaxf(x1, 0.f);
        acc2 += fmaxf(x2, 0.f);
        acc3 += fmaxf(x3, 0.f);
    }

    float l0 = acc0 - __bfloat162float(__float2bfloat16_rn(acc0));
    float l1 = acc1 - __bfloat162float(__float2bfloat16_rn(acc1));
    float l2 = acc2 - __bfloat162float(__float2bfloat16_rn(acc2));
    float l3 = acc3 - __bfloat162float(__float2bfloat16_rn(acc3));
    uint2 uh = make_uint2(pb2(acc0, acc1), pb2(acc2, acc3));
    uint2 ul = make_uint2(pb2(l0, l1), pb2(l2, l3));
    int g = lane >> 1;
    int didx = (n >> 7) * TILE_ELEMS + swz_idx(n & 127, g) + (lane & 1) * 4;
    *(uint2*)(g_sh + didx) = uh;
    *(uint2*)(g_sl + didx) = ul;
}

// ------------------------- GRU gates + BN + residual + bf16 out --------------
__global__ void gate_kernel(const float* __restrict__ gamma, const float* __restrict__ beta,
                            const float* __restrict__ mean, const float* __restrict__ var)
{
    int idx = blockIdx.x * blockDim.x + threadIdx.x;
    if (idx >= NNODES * 16) return;
    int n = idx >> 4;
    int q = idx & 15;
    int j0 = q * 8;
    const float* gi = g_gi + (size_t)n * 384 + j0;
    const float* gh = g_gh + (size_t)n * 384 + j0;
    float ir[8], iz[8], in_[8], hr[8], hz[8], hn[8], hv[8];
    *(float4*)(ir) = *(const float4*)(gi);         *(float4*)(ir + 4) = *(const float4*)(gi + 4);
    *(float4*)(iz) = *(const float4*)(gi + 128);   *(float4*)(iz + 4) = *(const float4*)(gi + 132);
    *(float4*)(in_) = *(const float4*)(gi + 256);  *(float4*)(in_ + 4) = *(const float4*)(gi + 260);
    *(float4*)(hr) = *(const float4*)(gh);         *(float4*)(hr + 4) = *(const float4*)(gh + 4);
    *(float4*)(hz) = *(const float4*)(gh + 128);   *(float4*)(hz + 4) = *(const float4*)(gh + 132);
    *(float4*)(hn) = *(const float4*)(gh + 256);   *(float4*)(hn + 4) = *(const float4*)(gh + 260);
    *(float4*)(hv) = *(const float4*)(g_h + (size_t)n * HID + j0);
    *(float4*)(hv + 4) = *(const float4*)(g_h + (size_t)n * HID + j0 + 4);
    float ov[8];
#pragma unroll
    for (int c = 0; c < 8; c++) {
        float r = sigm(ir[c] + hr[c]);
        float z = sigm(iz[c] + hz[c]);
        float nn = tanhf(in_[c] + r * hn[c]);
        float hnew = (1.f - z) * nn + z * hv[c];
        float bn = (hnew - mean[j0 + c]) * rsqrtf(var[j0 + c] + BN_EPS) * gamma[j0 + c]
                   + beta[j0 + c];
        ov[c] = hv[c] + bn;
    }
    *(float4*)(g_h + (size_t)n * HID + j0) = make_float4(ov[0], ov[1], ov[2], ov[3]);
    *(float4*)(g_h + (size_t)n * HID + j0 + 4) = make_float4(ov[4], ov[5], ov[6], ov[7]);
    uint4 uh, ul;
    split8(ov, uh, ul);
    int didx = (n >> 7) * TILE_ELEMS + swz_idx(n & 127, q);
    *(uint4*)(g_ah + didx) = uh;
    *(uint4*)(g_al + didx) = ul;
}

// ------------------------- readout -------------------------------------------
__device__ __forceinline__ unsigned enc_f(float f) {
    unsigned u = __float_as_uint(f);
    return (u & 0x80000000u) ? ~u : (u | 0x80000000u);
}

__global__ void readout_kernel(const int* __restrict__ batch) {
    int lane = threadIdx.x & 31;
    int n = (blockIdx.x * blockDim.x + threadIdx.x) >> 5;
    if (n >= NNODES) return;
    int g = __ldg(batch + n);
    float4 v = *(const float4*)(g_h + (size_t)n * HID + lane * 4);
    atomicAdd((float4*)(g_zsum + (size_t)g * HID) + lane, v);
    unsigned* mk = g_zmaxk + (size_t)g * HID + lane * 4;
    atomicMax(mk + 0, enc_f(v.x));
    atomicMax(mk + 1, enc_f(v.y));
    atomicMax(mk + 2, enc_f(v.z));
    atomicMax(mk + 3, enc_f(v.w));
    if (lane == 0) atomicAdd(&g_cnt[g], 1.f);
}

__global__ void final_kernel(const float* __restrict__ ro_w, const float* __restrict__ ro_b,
                             float* __restrict__ out)
{
    int gph = blockIdx.x;
    int j = threadIdx.x;
    __shared__ float smean[HID], smax[HID];
    float cntv = g_cnt[gph];
    float inv = 1.f / fmaxf(cntv, 1.f);
    bool has = cntv > 0.f;
    smean[j] = g_zsum[gph * HID + j] * inv;
    unsigned k = g_zmaxk[gph * HID + j];
    float mx = (k & 0x80000000u) ? __uint_as_float(k & 0x7fffffffu) : __uint_as_float(~k);
    smax[j] = has ? mx : 0.f;
    __syncthreads();
    float acc = ro_b[j];
#pragma unroll 4
    for (int kk = 0; kk < HID; kk++) {
        acc += smean[kk] * __ldg(ro_w + kk * HID + j);
        acc += smax[kk] * __ldg(ro_w + (HID + kk) * HID + j);
    }
    out[gph * HID + j] = fmaxf(acc, 0.f);
}

// ------------------------- launch --------------------------------------------
#define TG_DSMEM 196608

extern "C" void kernel_launch(void* const* d_in, const int* in_sizes, int n_in,
                              void* d_out, int out_size)
{
    const float* x     = (const float*)d_in[0];
    const int*   eidx  = (const int*)d_in[1];
    const float* eattr = (const float*)d_in[2];
    const int*   batch = (const int*)d_in[3];
    int base = (n_in == 21) ? 5 : 4;
    const float* lin_w = (const float*)d_in[base + 0];
    const float* lin_b = (const float*)d_in[base + 1];
    const float* mw1   = (const float*)d_in[base + 2];
    const float* mb1   = (const float*)d_in[base + 3];
    const float* mw2   = (const float*)d_in[base + 4];
    const float* mb2   = (const float*)d_in[base + 5];
    const float* bng   = (const float*)d_in[base + 6];
    const float* bnb   = (const float*)d_in[base + 7];
    const float* bnm   = (const float*)d_in[base + 8];
    const float* bnv   = (const float*)d_in[base + 9];
    const float* wih   = (const float*)d_in[base + 10];
    const float* whh   = (const float*)d_in[base + 11];
    const float* bih   = (const float*)d_in[base + 12];
    const float* bhh   = (const float*)d_in[base + 13];
    const float* ro_w  = (const float*)d_in[base + 14];
    const float* ro_b  = (const float*)d_in[base + 15];
    float* out = (float*)d_out;
    const int* src = eidx;
    const int* dst = eidx + NEDGES;

    float *hb, *pb, *gib, *ghb, *degb, *w2ib, *pkbias, *wihTb, *c2ib;
    __nv_bfloat16 *ahb, *alb, *shb, *slb;
    cudaGetSymbolAddress((void**)&hb, g_h);
    cudaGetSymbolAddress((void**)&pb, g_p);
    cudaGetSymbolAddress((void**)&gib, g_gi);
    cudaGetSymbolAddress((void**)&ghb, g_gh);
    cudaGetSymbolAddress((void**)&degb, g_deg);
    cudaGetSymbolAddress((void**)&w2ib, g_w2i);
    cudaGetSymbolAddress((void**)&pkbias, g_packbias);
    cudaGetSymbolAddress((void**)&wihTb, g_wihT);
    cudaGetSymbolAddress((void**)&ahb, g_ah);
    cudaGetSymbolAddress((void**)&alb, g_al);
    cudaGetSymbolAddress((void**)&shb, g_sh);
    cudaGetSymbolAddress((void**)&slb, g_sl);
    cudaGetSymbolAddress((void**)&c2ib, g_c2i);

    cudaFuncSetAttribute(tgemm, cudaFuncAttributeMaxDynamicSharedMemorySize, TG_DSMEM);

    // side stream + fork/join events (created once; no device-memory allocation)
    static cudaStream_t s2 = nullptr;
    static cudaEvent_t evF = nullptr, evJ = nullptr;
    if (s2 == nullptr) {
        cudaStreamCreateWithFlags(&s2, cudaStreamNonBlocking);
        cudaEventCreateWithFlags(&evF, cudaEventDisableTiming);
        cudaEventCreateWithFlags(&evJ, cudaEventDisableTiming);
    }

    int nblk1024 = (NNODES + 1023) / 1024;   // 49

    // ---- fork: CSR build chain on side stream (depends only on edge_index) --
    cudaEventRecord(evF, 0);
    cudaStreamWaitEvent(s2, evF, 0);
    csr_zero<<<(NNODES + 255) / 256, 256, 0, s2>>>();
    csr_count<<<(NEDGES + 255) / 256, 256, 0, s2>>>(dst);
    csr_scan1<<<nblk1024, 1024, 0, s2>>>();
    csr_scan2<<<1, 64, 0, s2>>>(nblk1024);
    csr_final<<<(NNODES + 255) / 256, 256, 0, s2>>>();
    csr_fill<<<(NEDGES + 255) / 256, 256, 0, s2>>>(src, dst);
    cudaEventRecord(evJ, s2);

    // ---- main stream: prep chain (depends only on x + weights) --------------
    prep_kernel<<<(MTILES * 128 * 16 + 255) / 256, 256>>>(mw1, mb1, whh, bhh, wih, mb2, x);
    sgemm128<<<dim3(1, 3, NL), 256>>>(mw2, wihTb, 128, 384, w2ib,
                                      HID * HID, HID * 384, HID * 384);
    prep_convB<<<(NBTILES * 2048 + 255) / 256, 256>>>(lin_w);
    tgemm<<<dim3(148, 1), 512, TG_DSMEM>>>(ahb, alb, 0,
                                           hb, 128, 1, nullptr, 0,
                                           lin_b, nullptr, nullptr, 1);
    conv_rows<<<(MTILES * 128 * 16 + 255) / 256, 256>>>(hb, ahb, alb);

    // ---- join: CSR results needed from first agg onward ---------------------
    cudaStreamWaitEvent(0, evJ, 0);

    for (int l = 0; l < NL; l++) {
        tgemm<<<dim3(37, 4), 512, TG_DSMEM>>>(ahb, alb, 1 + l * 4,
                                              pb, 128, 1, ghb, 384,
                                              pkbias + l * 512, nullptr, nullptr, 0);
        agg_kernel<<<(NNODES * 32 + 255) / 256, 256>>>(eattr,
                                                       mw1 + l * 144 * HID + 128 * HID);
        tgemm<<<dim3(49, 3), 512, TG_DSMEM>>>(shb, slb, 13 + l * 3,
                                              gib, 384, 3, nullptr, 0,
                                              bih + l * 384, degb, c2ib + l * 384, 0);
        gate_kernel<<<(NNODES * 16 + 255) / 256, 256>>>(bng + l * HID, bnb + l * HID,
                                                        bnm + l * HID, bnv + l * HID);
    }

    readout_kernel<<<(NNODES * 32 + 255) / 256, 256>>>(batch);
    final_kernel<<<NG, HID>>>(ro_w, ro_b, out);
    (void)in_sizes; (void)out_size;
}